// round 1
// baseline (speedup 1.0000x reference)
#include <cuda_runtime.h>
#include <cuda_bf16.h>
#include <math.h>

#define Bb      2
#define Ll      2048
#define HIDDEN_ 2048
#define PROJ_   8512
#define INTER_  4096
#define CONVD_  4352
#define NH_     64
#define HD_     64
#define ST_     128
#define NC_     8
#define CS_     256

// ---------------- static scratch (no allocations allowed) ----------------
__device__ float g_proj  [(size_t)Bb*Ll*PROJ_];          // 139.5 MB
__device__ float g_xbc   [(size_t)Bb*Ll*CONVD_];         //  71.3 MB
__device__ float g_y     [(size_t)Bb*Ll*INTER_];         //  67.1 MB
__device__ float g_states[(size_t)Bb*NC_*NH_*HD_*ST_];   //  33.5 MB
__device__ float g_prev  [(size_t)Bb*NC_*NH_*HD_*ST_];   //  33.5 MB
__device__ float g_cum   [(size_t)Bb*NH_*Ll];            //   1.0 MB
__device__ float g_alast [(size_t)Bb*NH_*NC_];
__device__ float g_g     [(size_t)Bb*Ll*INTER_];         //  67.1 MB

// ---------------- generic SGEMM: C[m,n] = sum_k A[m,k]*W[n,k] + bias[n] ----
// A: MxK row-major, W: NxK row-major. M % 128 == 0, K % 8 == 0. N guarded.
__global__ __launch_bounds__(256) void sgemm_bias_kernel(
    const float* __restrict__ A, const float* __restrict__ W,
    const float* __restrict__ bias, float* __restrict__ C,
    int M, int N, int K)
{
    __shared__ float As[8][128];
    __shared__ float Bs[8][128];
    const int tid = threadIdx.x;
    const int bm = blockIdx.y * 128;
    const int bn = blockIdx.x * 128;
    const int lr = tid >> 1;
    const int lc = (tid & 1) * 4;
    const int tx = tid & 15;
    const int ty = tid >> 4;

    const float* Ap = A + (size_t)(bm + lr) * K + lc;
    const float* Wp = W + (size_t)(bn + lr) * K + lc;
    const bool wv = (bn + lr) < N;

    float acc[8][8];
#pragma unroll
    for (int r = 0; r < 8; r++)
#pragma unroll
        for (int q = 0; q < 8; q++) acc[r][q] = 0.f;

    for (int k0 = 0; k0 < K; k0 += 8) {
        float4 av = *(const float4*)(Ap + k0);
        float4 wvv = wv ? *(const float4*)(Wp + k0) : make_float4(0.f, 0.f, 0.f, 0.f);
        __syncthreads();
        As[lc + 0][lr] = av.x;  As[lc + 1][lr] = av.y;
        As[lc + 2][lr] = av.z;  As[lc + 3][lr] = av.w;
        Bs[lc + 0][lr] = wvv.x; Bs[lc + 1][lr] = wvv.y;
        Bs[lc + 2][lr] = wvv.z; Bs[lc + 3][lr] = wvv.w;
        __syncthreads();
#pragma unroll
        for (int k = 0; k < 8; k++) {
            float4 a0 = *(const float4*)&As[k][ty * 8];
            float4 a1 = *(const float4*)&As[k][ty * 8 + 4];
            float4 b0 = *(const float4*)&Bs[k][tx * 8];
            float4 b1 = *(const float4*)&Bs[k][tx * 8 + 4];
            float a[8] = {a0.x, a0.y, a0.z, a0.w, a1.x, a1.y, a1.z, a1.w};
            float bb[8] = {b0.x, b0.y, b0.z, b0.w, b1.x, b1.y, b1.z, b1.w};
#pragma unroll
            for (int r = 0; r < 8; r++)
#pragma unroll
                for (int q = 0; q < 8; q++)
                    acc[r][q] = fmaf(a[r], bb[q], acc[r][q]);
        }
    }
#pragma unroll
    for (int r = 0; r < 8; r++) {
        int row = bm + ty * 8 + r;
#pragma unroll
        for (int q = 0; q < 8; q++) {
            int col = bn + tx * 8 + q;
            if (col < N)
                C[(size_t)row * N + col] = acc[r][q] + bias[col];
        }
    }
}

// ---------------- causal depthwise conv (K=4) + SiLU ----------------------
__global__ void conv_silu_kernel(const float* __restrict__ proj,
                                 const float* __restrict__ cw,
                                 float* __restrict__ xbc)
{
    int idx = blockIdx.x * 256 + threadIdx.x;
    if (idx >= Bb * Ll * CONVD_) return;
    int cidx = idx % CONVD_;
    int t = (idx / CONVD_) % Ll;
    int b = idx / (CONVD_ * Ll);
    const float* base = proj + (size_t)(b * Ll) * PROJ_ + INTER_ + cidx;
    float acc = 0.f;
#pragma unroll
    for (int j = 0; j < 4; j++) {
        int tt = t + j - 3;
        if (tt >= 0) acc = fmaf(base[(size_t)tt * PROJ_], cw[cidx * 4 + j], acc);
    }
    float sg = 1.f / (1.f + expf(-acc));
    xbc[idx] = acc * sg;
}

// ---------------- intra-chunk scan: Y_diag + per-chunk states -------------
// One block per (b, chunk, head). 256 threads.
__global__ __launch_bounds__(256, 2) void scan_intra_kernel(
    const float* __restrict__ proj, const float* __restrict__ xbc,
    const float* __restrict__ dt_bias, const float* __restrict__ A_log,
    float* __restrict__ ydiag, float* __restrict__ states,
    float* __restrict__ cumg, float* __restrict__ alast)
{
    const int h = blockIdx.x, c = blockIdx.y, b = blockIdx.z;
    const int tid = threadIdx.x;
    extern __shared__ float sm[];
    float* CsT = sm;                  // [128][68]  C^T tile (n-major)
    float* BsT = CsT + 128 * 68;      // [128][68]  B^T tile
    float* xsm = BsT + 128 * 68;      // [64][68]   x*dt tile
    float* Ps  = xsm + 64 * 68;       // [64][68]   attention tile
    float* dsh = Ps + 64 * 68;        // [256] dt
    float* cum = dsh + 256;           // [256] cumsum(A*dt)

    {
        float Ah = -expf(A_log[h]);
        float v = proj[(size_t)(b * Ll + c * CS_ + tid) * PROJ_ + (INTER_ + CONVD_) + h]
                + dt_bias[h];
        float dtv = (v > 20.f) ? v : log1pf(expf(v));
        dsh[tid] = dtv;
        cum[tid] = Ah * dtv;
    }
    __syncthreads();
    for (int off = 1; off < 256; off <<= 1) {
        float add = (tid >= off) ? cum[tid - off] : 0.f;
        __syncthreads();
        cum[tid] += add;
        __syncthreads();
    }
    cumg[(size_t)(b * NH_ + h) * Ll + c * CS_ + tid] = cum[tid];
    if (tid == 255) alast[(b * NH_ + h) * NC_ + c] = cum[255];

    const int tx = tid & 15, ty = tid >> 4;
    float stacc[4][8];
#pragma unroll
    for (int r = 0; r < 4; r++)
#pragma unroll
        for (int q = 0; q < 8; q++) stacc[r][q] = 0.f;

    const size_t rowbase = (size_t)(b * Ll + c * CS_);

    for (int i = 0; i < 4; i++) {
        // load C tile i (transposed)
        for (int idx = tid; idx < 64 * 128; idx += 256) {
            int tl = idx >> 7, n = idx & 127;
            CsT[n * 68 + tl] =
                xbc[(rowbase + i * 64 + tl) * CONVD_ + (INTER_ + ST_) + n];
        }
        float yacc[4][4];
#pragma unroll
        for (int r = 0; r < 4; r++)
#pragma unroll
            for (int q = 0; q < 4; q++) yacc[r][q] = 0.f;

        for (int j = 0; j <= i; j++) {
            __syncthreads();
            for (int idx = tid; idx < 64 * 128; idx += 256) {
                int sl = idx >> 7, n = idx & 127;
                BsT[n * 68 + sl] =
                    xbc[(rowbase + j * 64 + sl) * CONVD_ + INTER_ + n];
            }
            for (int idx = tid; idx < 64 * 64; idx += 256) {
                int sl = idx >> 6, p = idx & 63;
                xsm[sl * 68 + p] =
                    xbc[(rowbase + j * 64 + sl) * CONVD_ + h * HD_ + p]
                    * dsh[j * 64 + sl];
            }
            __syncthreads();

            if (j == i) {
                // states += B[s]^T * exp(cum_last - cum[s]) * (x[s]*dt[s])
                float clast = cum[255];
                int p0 = tx * 4, n0 = ty * 8;
                for (int sl = 0; sl < 64; sl++) {
                    float w = expf(clast - cum[i * 64 + sl]);
                    float4 x4 = *(const float4*)&xsm[sl * 68 + p0];
                    float xv[4] = {x4.x * w, x4.y * w, x4.z * w, x4.w * w};
#pragma unroll
                    for (int q = 0; q < 8; q++) {
                        float bv = BsT[(n0 + q) * 68 + sl];
#pragma unroll
                        for (int r = 0; r < 4; r++)
                            stacc[r][q] = fmaf(xv[r], bv, stacc[r][q]);
                    }
                }
            }

            // P[t][s] = sum_n C[t][n]*B[s][n]
            float pf[4][4];
#pragma unroll
            for (int r = 0; r < 4; r++)
#pragma unroll
                for (int q = 0; q < 4; q++) pf[r][q] = 0.f;
            {
                int t0 = ty * 4, s0 = tx * 4;
                for (int n = 0; n < 128; n++) {
                    float4 c4 = *(const float4*)&CsT[n * 68 + t0];
                    float4 b4 = *(const float4*)&BsT[n * 68 + s0];
                    float cr[4] = {c4.x, c4.y, c4.z, c4.w};
                    float br[4] = {b4.x, b4.y, b4.z, b4.w};
#pragma unroll
                    for (int r = 0; r < 4; r++)
#pragma unroll
                        for (int q = 0; q < 4; q++)
                            pf[r][q] = fmaf(cr[r], br[q], pf[r][q]);
                }
                // apply decay weights (exponent always <= 0: safe)
#pragma unroll
                for (int r = 0; r < 4; r++) {
                    int tg = i * 64 + t0 + r;
                    float ct = cum[tg];
                    float4 o;
                    float* po = (float*)&o;
#pragma unroll
                    for (int q = 0; q < 4; q++) {
                        int sg = j * 64 + s0 + q;
                        float w = (sg <= tg) ? expf(ct - cum[sg]) : 0.f;
                        po[q] = pf[r][q] * w;
                    }
                    *(float4*)&Ps[(t0 + r) * 68 + s0] = o;
                }
            }
            __syncthreads();
            // Y_i += Pw @ (x*dt)
            {
                int t0 = ty * 4, p0 = tx * 4;
                for (int sl = 0; sl < 64; sl++) {
                    float4 x4 = *(const float4*)&xsm[sl * 68 + p0];
#pragma unroll
                    for (int r = 0; r < 4; r++) {
                        float pv = Ps[(t0 + r) * 68 + sl];
                        yacc[r][0] = fmaf(pv, x4.x, yacc[r][0]);
                        yacc[r][1] = fmaf(pv, x4.y, yacc[r][1]);
                        yacc[r][2] = fmaf(pv, x4.z, yacc[r][2]);
                        yacc[r][3] = fmaf(pv, x4.w, yacc[r][3]);
                    }
                }
            }
        }
        // write Y_diag tile i  (layout: (b, l, h, p))
        {
            int t0 = ty * 4, p0 = tx * 4;
#pragma unroll
            for (int r = 0; r < 4; r++) {
                size_t tg = rowbase + i * 64 + t0 + r;
                float4 o = {yacc[r][0], yacc[r][1], yacc[r][2], yacc[r][3]};
                *(float4*)&ydiag[(tg * NH_ + h) * HD_ + p0] = o;
            }
        }
    }
    // write states (layout: (b, c, h, p, n))
    {
        int p0 = tx * 4, n0 = ty * 8;
        size_t base = ((size_t)((b * NC_ + c) * NH_ + h)) * HD_;
#pragma unroll
        for (int r = 0; r < 4; r++) {
            float4 o0 = {stacc[r][0], stacc[r][1], stacc[r][2], stacc[r][3]};
            float4 o1 = {stacc[r][4], stacc[r][5], stacc[r][6], stacc[r][7]};
            float* dst = states + (base + p0 + r) * ST_ + n0;
            *(float4*)dst = o0;
            *(float4*)(dst + 4) = o1;
        }
    }
}

// ---------------- inter-chunk recurrence -----------------------------------
__global__ void interchunk_kernel(const float* __restrict__ states,
                                  const float* __restrict__ alast,
                                  float* __restrict__ prev)
{
    int bh = blockIdx.x;
    int b = bh >> 6, h = bh & 63;
    float dec[NC_];
#pragma unroll
    for (int c = 0; c < NC_; c++)
        dec[c] = expf(alast[(b * NH_ + h) * NC_ + c]);
    for (int e = threadIdx.x; e < HD_ * ST_; e += 256) {
        float run = 0.f;
#pragma unroll
        for (int c = 0; c < NC_; c++) {
            size_t idx = ((size_t)((b * NC_ + c) * NH_ + h)) * (HD_ * ST_) + e;
            prev[idx] = run;
            run = fmaf(run, dec[c] - 1.f, run) ;  // run*dec[c]
            run = run + states[idx];
        }
    }
}

// ---------------- Y_off + D-skip, accumulate into y ------------------------
__global__ __launch_bounds__(256, 2) void scan_off_kernel(
    const float* __restrict__ xbc, const float* __restrict__ cumg,
    const float* __restrict__ prev, const float* __restrict__ Dv,
    float* __restrict__ y)
{
    const int h = blockIdx.x, c = blockIdx.y, b = blockIdx.z;
    const int tid = threadIdx.x;
    extern __shared__ float sm[];
    float* pvs = sm;                  // [64][129] prev (p, n)
    float* CsT = pvs + 64 * 129;      // [128][68]
    size_t sbase = ((size_t)((b * NC_ + c) * NH_ + h)) * (HD_ * ST_);
    for (int idx = tid; idx < 64 * 128; idx += 256) {
        int p = idx >> 7, n = idx & 127;
        pvs[p * 129 + n] = prev[sbase + idx];
    }
    const float Dh = Dv[h];
    const int tx = tid & 15, ty = tid >> 4;
    const size_t rowbase = (size_t)(b * Ll + c * CS_);
    for (int ti = 0; ti < 4; ti++) {
        __syncthreads();
        for (int idx = tid; idx < 64 * 128; idx += 256) {
            int tl = idx >> 7, n = idx & 127;
            CsT[n * 68 + tl] =
                xbc[(rowbase + ti * 64 + tl) * CONVD_ + (INTER_ + ST_) + n];
        }
        __syncthreads();
        int t0 = ty * 4, p0 = tx * 4;
        float acc[4][4];
#pragma unroll
        for (int r = 0; r < 4; r++)
#pragma unroll
            for (int q = 0; q < 4; q++) acc[r][q] = 0.f;
        for (int n = 0; n < 128; n++) {
            float4 c4 = *(const float4*)&CsT[n * 68 + t0];
            float cr[4] = {c4.x, c4.y, c4.z, c4.w};
            float pv[4];
#pragma unroll
            for (int q = 0; q < 4; q++) pv[q] = pvs[(p0 + q) * 129 + n];
#pragma unroll
            for (int r = 0; r < 4; r++)
#pragma unroll
                for (int q = 0; q < 4; q++)
                    acc[r][q] = fmaf(cr[r], pv[q], acc[r][q]);
        }
#pragma unroll
        for (int r = 0; r < 4; r++) {
            int tloc = c * CS_ + ti * 64 + t0 + r;
            size_t tg = rowbase + ti * 64 + t0 + r;
            float e = expf(cumg[(size_t)(b * NH_ + h) * Ll + tloc]);
            float* yp = y + (tg * NH_ + h) * HD_ + p0;
            float4 yv = *(float4*)yp;
            const float4 xv = *(const float4*)&xbc[tg * CONVD_ + h * HD_ + p0];
            yv.x += acc[r][0] * e + Dh * xv.x;
            yv.y += acc[r][1] * e + Dh * xv.y;
            yv.z += acc[r][2] * e + Dh * xv.z;
            yv.w += acc[r][3] * e + Dh * xv.w;
            *(float4*)yp = yv;
        }
    }
}

// ---------------- gated RMSNorm --------------------------------------------
__global__ __launch_bounds__(256) void gated_norm_kernel(
    const float* __restrict__ proj, const float* __restrict__ y,
    const float* __restrict__ nw, float* __restrict__ g)
{
    int row = blockIdx.x;
    int tid = threadIdx.x;
    float gv[16];
    float ss = 0.f;
    const float* yr = y + (size_t)row * INTER_;
    const float* gr = proj + (size_t)row * PROJ_;
#pragma unroll
    for (int k = 0; k < 16; k++) {
        int idx = tid + k * 256;
        float gt = gr[idx];
        float s = 1.f / (1.f + expf(-gt));
        float v = yr[idx] * gt * s;
        gv[k] = v;
        ss = fmaf(v, v, ss);
    }
    __shared__ float red[256];
    red[tid] = ss;
    __syncthreads();
    for (int off = 128; off > 0; off >>= 1) {
        if (tid < off) red[tid] += red[tid + off];
        __syncthreads();
    }
    float scale = rsqrtf(red[0] / (float)INTER_ + 1e-5f);
#pragma unroll
    for (int k = 0; k < 16; k++) {
        int idx = tid + k * 256;
        g[(size_t)row * INTER_ + idx] = gv[k] * scale * nw[idx];
    }
}

// ---------------- launch ----------------------------------------------------
extern "C" void kernel_launch(void* const* d_in, const int* in_sizes, int n_in,
                              void* d_out, int out_size)
{
    const float* hidden  = (const float*)d_in[0];
    const float* in_w    = (const float*)d_in[1];
    const float* in_b    = (const float*)d_in[2];
    const float* conv_w  = (const float*)d_in[3];
    const float* dt_bias = (const float*)d_in[4];
    const float* A_log   = (const float*)d_in[5];
    const float* Dv      = (const float*)d_in[6];
    const float* norm_w  = (const float*)d_in[7];
    const float* out_w   = (const float*)d_in[8];
    const float* out_b   = (const float*)d_in[9];
    float* out = (float*)d_out;

    float *proj, *xbc, *y, *states, *prev, *cum, *al, *g;
    cudaGetSymbolAddress((void**)&proj,   g_proj);
    cudaGetSymbolAddress((void**)&xbc,    g_xbc);
    cudaGetSymbolAddress((void**)&y,      g_y);
    cudaGetSymbolAddress((void**)&states, g_states);
    cudaGetSymbolAddress((void**)&prev,   g_prev);
    cudaGetSymbolAddress((void**)&cum,    g_cum);
    cudaGetSymbolAddress((void**)&al,     g_alast);
    cudaGetSymbolAddress((void**)&g,      g_g);

    const int SMEM_INTRA = (128 * 68 * 2 + 64 * 68 * 2 + 512) * 4;   // 106496 B
    const int SMEM_OFF   = (64 * 129 + 128 * 68) * 4;                //  67840 B
    cudaFuncSetAttribute(scan_intra_kernel,
                         cudaFuncAttributeMaxDynamicSharedMemorySize, SMEM_INTRA);
    cudaFuncSetAttribute(scan_off_kernel,
                         cudaFuncAttributeMaxDynamicSharedMemorySize, SMEM_OFF);

    const int M = Bb * Ll;  // 4096

    // 1. in_proj GEMM + bias
    sgemm_bias_kernel<<<dim3((PROJ_ + 127) / 128, M / 128), 256>>>(
        hidden, in_w, in_b, proj, M, PROJ_, HIDDEN_);

    // 2. causal depthwise conv + SiLU
    conv_silu_kernel<<<(Bb * Ll * CONVD_ + 255) / 256, 256>>>(proj, conv_w, xbc);

    // 3. intra-chunk scan
    scan_intra_kernel<<<dim3(NH_, NC_, Bb), 256, SMEM_INTRA>>>(
        proj, xbc, dt_bias, A_log, y, states, cum, al);

    // 4. inter-chunk recurrence
    interchunk_kernel<<<Bb * NH_, 256>>>(states, al, prev);

    // 5. inter-chunk output contribution + D skip
    scan_off_kernel<<<dim3(NH_, NC_, Bb), 256, SMEM_OFF>>>(xbc, cum, prev, Dv, y);

    // 6. gated RMSNorm
    gated_norm_kernel<<<M, 256>>>(proj, y, norm_w, g);

    // 7. out_proj GEMM + bias
    sgemm_bias_kernel<<<dim3(HIDDEN_ / 128, M / 128), 256>>>(
        g, out_w, out_b, out, M, HIDDEN_, INTER_);
}

// round 3
// speedup vs baseline: 2.2642x; 2.2642x over previous
#include <cuda_runtime.h>
#include <cuda_bf16.h>
#include <math.h>
#include <cstdint>

#define Bb      2
#define Ll      2048
#define HIDDEN_ 2048
#define PROJ_   8512
#define INTER_  4096
#define CONVD_  4352
#define NH_     64
#define HD_     64
#define ST_     128
#define NC_     8
#define CS_     256
#define MT      (Bb*Ll)      // 4096
#define NP1     8576         // PROJ_ padded to 67*128

// ---------------- static scratch (no allocations allowed) ----------------
__device__ float g_proj  [(size_t)MT*PROJ_];
__device__ float g_xbc   [(size_t)MT*CONVD_];
__device__ float g_y     [(size_t)MT*INTER_];
__device__ float g_states[(size_t)Bb*NC_*NH_*HD_*ST_];
__device__ float g_prev  [(size_t)Bb*NC_*NH_*HD_*ST_];
__device__ float g_cum   [(size_t)Bb*NH_*Ll];
__device__ float g_alast [(size_t)Bb*NH_*NC_];
__device__ __nv_bfloat16 g_Ah [(size_t)MT*INTER_];
__device__ __nv_bfloat16 g_Al [(size_t)MT*INTER_];
__device__ __nv_bfloat16 g_W1h[(size_t)NP1*HIDDEN_];
__device__ __nv_bfloat16 g_W1l[(size_t)NP1*HIDDEN_];
__device__ __nv_bfloat16 g_W2h[(size_t)HIDDEN_*INTER_];
__device__ __nv_bfloat16 g_W2l[(size_t)HIDDEN_*INTER_];

// ======================= warp-MMA helpers (sm_80 path) ====================
__device__ __forceinline__ uint32_t cvta_smem(const void* p) {
    uint32_t a;
    asm("{ .reg .u64 t; cvta.to.shared.u64 t, %1; cvt.u32.u64 %0, t; }"
        : "=r"(a) : "l"(p));
    return a;
}

__device__ __forceinline__ void ldsm4(uint32_t* r, uint32_t addr) {
    asm volatile("ldmatrix.sync.aligned.m8n8.x4.shared.b16 {%0,%1,%2,%3}, [%4];"
                 : "=r"(r[0]), "=r"(r[1]), "=r"(r[2]), "=r"(r[3]) : "r"(addr));
}

__device__ __forceinline__ void mma16816(float* c, const uint32_t* a,
                                         uint32_t b0, uint32_t b1) {
    asm volatile(
        "mma.sync.aligned.m16n8k16.row.col.f32.bf16.bf16.f32 "
        "{%0,%1,%2,%3}, {%4,%5,%6,%7}, {%8,%9}, {%0,%1,%2,%3};"
        : "+f"(c[0]), "+f"(c[1]), "+f"(c[2]), "+f"(c[3])
        : "r"(a[0]), "r"(a[1]), "r"(a[2]), "r"(a[3]), "r"(b0), "r"(b1));
}

#define CPASYNC16(sa, ga) \
    asm volatile("cp.async.cg.shared.global [%0], [%1], 16;" :: "r"(sa), "l"(ga) : "memory")

#define TILEB  16384u
#define STAGEB 65536u
#define GSMEM  (1024 + 3*65536)

__device__ __forceinline__ void gemm_load_chunk(
    uint32_t tb, int s, int c,
    const __nv_bfloat16* __restrict__ Ah, const __nv_bfloat16* __restrict__ Al,
    const __nv_bfloat16* __restrict__ Wh, const __nv_bfloat16* __restrict__ Wl,
    size_t arow, size_t brow, int K, int tid)
{
    const int seg = tid & 7, r0 = tid >> 3;
    uint32_t stb = tb + (uint32_t)s * STAGEB;
    size_t ko = ((size_t)c << 6) + (size_t)(seg << 3);
#pragma unroll
    for (int t = 0; t < 4; t++) {
        int r = r0 + 32 * t;
        uint32_t off = (uint32_t)(r * 128 + seg * 16);
        uint32_t so = off ^ ((off >> 3) & 0x70);
        size_t ra = (arow + r) * (size_t)K + ko;
        size_t rb = (brow + r) * (size_t)K + ko;
        CPASYNC16(stb + so,             Ah + ra);
        CPASYNC16(stb + TILEB + so,     Al + ra);
        CPASYNC16(stb + 2*TILEB + so,   Wh + rb);
        CPASYNC16(stb + 3*TILEB + so,   Wl + rb);
    }
    asm volatile("cp.async.commit_group;" ::: "memory");
}

// =========================================================================
// Split-bf16 tensor-core GEMM via mma.sync: C = A*W^T + bias
// A = Ah+Al (M x K), W = Wh+Wl (Npad x K). BM=BN=128, BK=64, 3 stages.
// 8 warps: warp (wm, wn) owns 32(M) x 64(N).
// =========================================================================
__global__ __launch_bounds__(256, 1)
void tc_gemm_bias(
    const __nv_bfloat16* __restrict__ Ah, const __nv_bfloat16* __restrict__ Al,
    const __nv_bfloat16* __restrict__ Wh, const __nv_bfloat16* __restrict__ Wl,
    const float* __restrict__ bias, float* __restrict__ C, int N, int K)
{
    extern __shared__ __align__(128) char smem[];
    const int tid = threadIdx.x;
    const int lid = tid & 31, wid = tid >> 5;
    uint32_t sb = cvta_smem(smem);
    uint32_t tb = (sb + 1023u) & ~1023u;

    const size_t arow = (size_t)blockIdx.y * 128;
    const size_t brow = (size_t)blockIdx.x * 128;
    const int NCH = K >> 6;

    const int wm = wid & 3, wn = wid >> 2;
    const int m0 = wm * 32, n0 = wn * 64;
    const int lr  = lid & 15;            // ldmatrix row within 16
    const int lkb = (lid >> 4) * 16;     // ldmatrix col byte offset

    float acc[2][8][4];
#pragma unroll
    for (int mi = 0; mi < 2; mi++)
#pragma unroll
        for (int nj = 0; nj < 8; nj++)
#pragma unroll
            for (int q = 0; q < 4; q++) acc[mi][nj][q] = 0.f;

    // per-lane swizzled smem offsets (row part), for A (m) and B (n) tiles
    uint32_t aoff[2], boff[4];
#pragma unroll
    for (int mi = 0; mi < 2; mi++) {
        int row = m0 + mi * 16 + lr;
        aoff[mi] = (uint32_t)(row * 128) + (uint32_t)(((row & 7) * 16) ^ lkb);
    }
#pragma unroll
    for (int ni = 0; ni < 4; ni++) {
        int row = n0 + ni * 16 + lr;
        boff[ni] = (uint32_t)(row * 128) + (uint32_t)(((row & 7) * 16) ^ lkb);
    }
    const uint32_t sxor = (uint32_t)(((m0 + lr) & 7) * 16); // just to note pattern
    (void)sxor;

    gemm_load_chunk(tb, 0, 0, Ah, Al, Wh, Wl, arow, brow, K, tid);
    gemm_load_chunk(tb, 1, 1, Ah, Al, Wh, Wl, arow, brow, K, tid);

    for (int c = 0; c < NCH; c++) {
        if (c + 1 < NCH) asm volatile("cp.async.wait_group 1;" ::: "memory");
        else             asm volatile("cp.async.wait_group 0;" ::: "memory");
        __syncthreads();
        if (c + 2 < NCH)
            gemm_load_chunk(tb, (c + 2) % 3, c + 2, Ah, Al, Wh, Wl, arow, brow, K, tid);

        uint32_t stb = tb + (uint32_t)(c % 3) * STAGEB;
#pragma unroll
        for (int kk = 0; kk < 4; kk++) {
            // NOTE: xor by kk*32 is equivalent to adding within the 128B row
            // because lkb in {0,16} and kk*32 in {0,32,64,96} touch disjoint bits.
            uint32_t kx = (uint32_t)(kk * 32);
            uint32_t a_h[2][4], a_l[2][4];
#pragma unroll
            for (int mi = 0; mi < 2; mi++) {
                uint32_t ad = stb + (aoff[mi] ^ kx);
                ldsm4(a_h[mi], ad);
                ldsm4(a_l[mi], ad + TILEB);
            }
            uint32_t b_h[4][4], b_l[4][4];
#pragma unroll
            for (int ni = 0; ni < 4; ni++) {
                uint32_t bd = stb + (boff[ni] ^ kx);
                ldsm4(b_h[ni], bd + 2*TILEB);
                ldsm4(b_l[ni], bd + 3*TILEB);
            }
#pragma unroll
            for (int mi = 0; mi < 2; mi++)
#pragma unroll
                for (int ni = 0; ni < 4; ni++) {
                    // n-sub 0: regs {0,2}; n-sub 1: regs {1,3}
                    mma16816(acc[mi][2*ni],   a_h[mi], b_h[ni][0], b_h[ni][2]);
                    mma16816(acc[mi][2*ni+1], a_h[mi], b_h[ni][1], b_h[ni][3]);
                    mma16816(acc[mi][2*ni],   a_h[mi], b_l[ni][0], b_l[ni][2]);
                    mma16816(acc[mi][2*ni+1], a_h[mi], b_l[ni][1], b_l[ni][3]);
                    mma16816(acc[mi][2*ni],   a_l[mi], b_h[ni][0], b_h[ni][2]);
                    mma16816(acc[mi][2*ni+1], a_l[mi], b_h[ni][1], b_h[ni][3]);
                }
        }
        __syncthreads();
    }

    // epilogue: c frag (m16n8): rows lid/4 (+8), cols 2*(lid%3... lid&3)
    const int er = lid >> 2;
    const int ec = (lid & 3) * 2;
#pragma unroll
    for (int mi = 0; mi < 2; mi++) {
        int grow0 = (int)arow + m0 + mi * 16 + er;
#pragma unroll
        for (int nj = 0; nj < 8; nj++) {
            int gcol = (int)brow + n0 + nj * 8 + ec;
            if (gcol + 1 < N) {
                float b0 = __ldg(&bias[gcol]), b1 = __ldg(&bias[gcol + 1]);
                float2 v0 = {acc[mi][nj][0] + b0, acc[mi][nj][1] + b1};
                float2 v1 = {acc[mi][nj][2] + b0, acc[mi][nj][3] + b1};
                *(float2*)&C[(size_t)grow0 * N + gcol] = v0;
                *(float2*)&C[(size_t)(grow0 + 8) * N + gcol] = v1;
            } else if (gcol < N) {
                float b0 = __ldg(&bias[gcol]);
                C[(size_t)grow0 * N + gcol] = acc[mi][nj][0] + b0;
                C[(size_t)(grow0 + 8) * N + gcol] = acc[mi][nj][2] + b0;
            }
        }
    }
}

// ---------------- fp32 -> split bf16 conversion ---------------------------
__global__ void cvt_split_kernel(const float4* __restrict__ src,
                                 __nv_bfloat162* __restrict__ hi,
                                 __nv_bfloat162* __restrict__ lo,
                                 size_t n4v, size_t n4t)
{
    size_t i = (size_t)blockIdx.x * blockDim.x + threadIdx.x;
    size_t stride = (size_t)gridDim.x * blockDim.x;
    for (; i < n4t; i += stride) {
        float4 v = (i < n4v) ? src[i] : make_float4(0.f, 0.f, 0.f, 0.f);
        __nv_bfloat16 h0 = __float2bfloat16(v.x), h1 = __float2bfloat16(v.y);
        __nv_bfloat16 h2 = __float2bfloat16(v.z), h3 = __float2bfloat16(v.w);
        hi[2*i]   = __nv_bfloat162(h0, h1);
        hi[2*i+1] = __nv_bfloat162(h2, h3);
        lo[2*i]   = __nv_bfloat162(__float2bfloat16(v.x - __bfloat162float(h0)),
                                   __float2bfloat16(v.y - __bfloat162float(h1)));
        lo[2*i+1] = __nv_bfloat162(__float2bfloat16(v.z - __bfloat162float(h2)),
                                   __float2bfloat16(v.w - __bfloat162float(h3)));
    }
}

// ---------------- causal depthwise conv (K=4) + SiLU ----------------------
__global__ void conv_silu_kernel(const float* __restrict__ proj,
                                 const float* __restrict__ cw,
                                 float* __restrict__ xbc)
{
    int idx = blockIdx.x * 256 + threadIdx.x;
    if (idx >= Bb * Ll * CONVD_) return;
    int cidx = idx % CONVD_;
    int t = (idx / CONVD_) % Ll;
    int b = idx / (CONVD_ * Ll);
    const float* base = proj + (size_t)(b * Ll) * PROJ_ + INTER_ + cidx;
    float acc = 0.f;
#pragma unroll
    for (int j = 0; j < 4; j++) {
        int tt = t + j - 3;
        if (tt >= 0) acc = fmaf(base[(size_t)tt * PROJ_], cw[cidx * 4 + j], acc);
    }
    float sg = 1.f / (1.f + expf(-acc));
    xbc[idx] = acc * sg;
}

// ---------------- intra-chunk scan: Y_diag + per-chunk states -------------
__global__ __launch_bounds__(256, 2) void scan_intra_kernel(
    const float* __restrict__ proj, const float* __restrict__ xbc,
    const float* __restrict__ dt_bias, const float* __restrict__ A_log,
    float* __restrict__ ydiag, float* __restrict__ states,
    float* __restrict__ cumg, float* __restrict__ alast)
{
    const int h = blockIdx.x, c = blockIdx.y, b = blockIdx.z;
    const int tid = threadIdx.x;
    extern __shared__ float sm[];
    float* CsT = sm;
    float* BsT = CsT + 128 * 68;
    float* xsm = BsT + 128 * 68;
    float* Ps  = xsm + 64 * 68;
    float* dsh = Ps + 64 * 68;
    float* cum = dsh + 256;

    {
        float Ah = -expf(A_log[h]);
        float v = proj[(size_t)(b * Ll + c * CS_ + tid) * PROJ_ + (INTER_ + CONVD_) + h]
                + dt_bias[h];
        float dtv = (v > 20.f) ? v : log1pf(expf(v));
        dsh[tid] = dtv;
        cum[tid] = Ah * dtv;
    }
    __syncthreads();
    for (int off = 1; off < 256; off <<= 1) {
        float add = (tid >= off) ? cum[tid - off] : 0.f;
        __syncthreads();
        cum[tid] += add;
        __syncthreads();
    }
    cumg[(size_t)(b * NH_ + h) * Ll + c * CS_ + tid] = cum[tid];
    if (tid == 255) alast[(b * NH_ + h) * NC_ + c] = cum[255];

    const int tx = tid & 15, ty = tid >> 4;
    float stacc[4][8];
#pragma unroll
    for (int r = 0; r < 4; r++)
#pragma unroll
        for (int q = 0; q < 8; q++) stacc[r][q] = 0.f;

    const size_t rowbase = (size_t)(b * Ll + c * CS_);

    for (int i = 0; i < 4; i++) {
        for (int idx = tid; idx < 64 * 128; idx += 256) {
            int tl = idx >> 7, n = idx & 127;
            CsT[n * 68 + tl] =
                xbc[(rowbase + i * 64 + tl) * CONVD_ + (INTER_ + ST_) + n];
        }
        float yacc[4][4];
#pragma unroll
        for (int r = 0; r < 4; r++)
#pragma unroll
            for (int q = 0; q < 4; q++) yacc[r][q] = 0.f;

        for (int j = 0; j <= i; j++) {
            __syncthreads();
            for (int idx = tid; idx < 64 * 128; idx += 256) {
                int sl = idx >> 7, n = idx & 127;
                BsT[n * 68 + sl] =
                    xbc[(rowbase + j * 64 + sl) * CONVD_ + INTER_ + n];
            }
            for (int idx = tid; idx < 64 * 64; idx += 256) {
                int sl = idx >> 6, p = idx & 63;
                xsm[sl * 68 + p] =
                    xbc[(rowbase + j * 64 + sl) * CONVD_ + h * HD_ + p]
                    * dsh[j * 64 + sl];
            }
            __syncthreads();

            if (j == i) {
                float clast = cum[255];
                int p0 = tx * 4, n0 = ty * 8;
                for (int sl = 0; sl < 64; sl++) {
                    float w = expf(clast - cum[i * 64 + sl]);
                    float4 x4 = *(const float4*)&xsm[sl * 68 + p0];
                    float xv[4] = {x4.x * w, x4.y * w, x4.z * w, x4.w * w};
#pragma unroll
                    for (int q = 0; q < 8; q++) {
                        float bv = BsT[(n0 + q) * 68 + sl];
#pragma unroll
                        for (int r = 0; r < 4; r++)
                            stacc[r][q] = fmaf(xv[r], bv, stacc[r][q]);
                    }
                }
            }

            float pf[4][4];
#pragma unroll
            for (int r = 0; r < 4; r++)
#pragma unroll
                for (int q = 0; q < 4; q++) pf[r][q] = 0.f;
            {
                int t0 = ty * 4, s0 = tx * 4;
                for (int n = 0; n < 128; n++) {
                    float4 c4 = *(const float4*)&CsT[n * 68 + t0];
                    float4 b4 = *(const float4*)&BsT[n * 68 + s0];
                    float cr[4] = {c4.x, c4.y, c4.z, c4.w};
                    float br[4] = {b4.x, b4.y, b4.z, b4.w};
#pragma unroll
                    for (int r = 0; r < 4; r++)
#pragma unroll
                        for (int q = 0; q < 4; q++)
                            pf[r][q] = fmaf(cr[r], br[q], pf[r][q]);
                }
#pragma unroll
                for (int r = 0; r < 4; r++) {
                    int tg = i * 64 + t0 + r;
                    float ct = cum[tg];
                    float4 o;
                    float* po = (float*)&o;
#pragma unroll
                    for (int q = 0; q < 4; q++) {
                        int sg = j * 64 + s0 + q;
                        float w = (sg <= tg) ? expf(ct - cum[sg]) : 0.f;
                        po[q] = pf[r][q] * w;
                    }
                    *(float4*)&Ps[(t0 + r) * 68 + s0] = o;
                }
            }
            __syncthreads();
            {
                int t0 = ty * 4, p0 = tx * 4;
                for (int sl = 0; sl < 64; sl++) {
                    float4 x4 = *(const float4*)&xsm[sl * 68 + p0];
#pragma unroll
                    for (int r = 0; r < 4; r++) {
                        float pv = Ps[(t0 + r) * 68 + sl];
                        yacc[r][0] = fmaf(pv, x4.x, yacc[r][0]);
                        yacc[r][1] = fmaf(pv, x4.y, yacc[r][1]);
                        yacc[r][2] = fmaf(pv, x4.z, yacc[r][2]);
                        yacc[r][3] = fmaf(pv, x4.w, yacc[r][3]);
                    }
                }
            }
        }
        {
            int t0 = ty * 4, p0 = tx * 4;
#pragma unroll
            for (int r = 0; r < 4; r++) {
                size_t tg = rowbase + i * 64 + t0 + r;
                float4 o = {yacc[r][0], yacc[r][1], yacc[r][2], yacc[r][3]};
                *(float4*)&ydiag[(tg * NH_ + h) * HD_ + p0] = o;
            }
        }
    }
    {
        int p0 = tx * 4, n0 = ty * 8;
        size_t base = ((size_t)((b * NC_ + c) * NH_ + h)) * HD_;
#pragma unroll
        for (int r = 0; r < 4; r++) {
            float4 o0 = {stacc[r][0], stacc[r][1], stacc[r][2], stacc[r][3]};
            float4 o1 = {stacc[r][4], stacc[r][5], stacc[r][6], stacc[r][7]};
            float* dst = states + (base + p0 + r) * ST_ + n0;
            *(float4*)dst = o0;
            *(float4*)(dst + 4) = o1;
        }
    }
}

// ---------------- inter-chunk recurrence -----------------------------------
__global__ void interchunk_kernel(const float* __restrict__ states,
                                  const float* __restrict__ alast,
                                  float* __restrict__ prev)
{
    int bh = blockIdx.x;
    int b = bh >> 6, h = bh & 63;
    float dec[NC_];
#pragma unroll
    for (int c = 0; c < NC_; c++)
        dec[c] = expf(alast[(b * NH_ + h) * NC_ + c]);
    for (int e = threadIdx.x; e < HD_ * ST_; e += 256) {
        float run = 0.f;
#pragma unroll
        for (int c = 0; c < NC_; c++) {
            size_t idx = ((size_t)((b * NC_ + c) * NH_ + h)) * (HD_ * ST_) + e;
            prev[idx] = run;
            run = fmaf(run, dec[c] - 1.f, run);
            run = run + states[idx];
        }
    }
}

// ---------------- Y_off + D-skip, accumulate into y ------------------------
__global__ __launch_bounds__(256, 2) void scan_off_kernel(
    const float* __restrict__ xbc, const float* __restrict__ cumg,
    const float* __restrict__ prev, const float* __restrict__ Dv,
    float* __restrict__ y)
{
    const int h = blockIdx.x, c = blockIdx.y, b = blockIdx.z;
    const int tid = threadIdx.x;
    extern __shared__ float sm[];
    float* pvs = sm;
    float* CsT = pvs + 64 * 129;
    size_t sbase = ((size_t)((b * NC_ + c) * NH_ + h)) * (HD_ * ST_);
    for (int idx = tid; idx < 64 * 128; idx += 256) {
        int p = idx >> 7, n = idx & 127;
        pvs[p * 129 + n] = prev[sbase + idx];
    }
    const float Dh = Dv[h];
    const int tx = tid & 15, ty = tid >> 4;
    const size_t rowbase = (size_t)(b * Ll + c * CS_);
    for (int ti = 0; ti < 4; ti++) {
        __syncthreads();
        for (int idx = tid; idx < 64 * 128; idx += 256) {
            int tl = idx >> 7, n = idx & 127;
            CsT[n * 68 + tl] =
                xbc[(rowbase + ti * 64 + tl) * CONVD_ + (INTER_ + ST_) + n];
        }
        __syncthreads();
        int t0 = ty * 4, p0 = tx * 4;
        float acc[4][4];
#pragma unroll
        for (int r = 0; r < 4; r++)
#pragma unroll
            for (int q = 0; q < 4; q++) acc[r][q] = 0.f;
        for (int n = 0; n < 128; n++) {
            float4 c4 = *(const float4*)&CsT[n * 68 + t0];
            float cr[4] = {c4.x, c4.y, c4.z, c4.w};
            float pv[4];
#pragma unroll
            for (int q = 0; q < 4; q++) pv[q] = pvs[(p0 + q) * 129 + n];
#pragma unroll
            for (int r = 0; r < 4; r++)
#pragma unroll
                for (int q = 0; q < 4; q++)
                    acc[r][q] = fmaf(cr[r], pv[q], acc[r][q]);
        }
#pragma unroll
        for (int r = 0; r < 4; r++) {
            int tloc = c * CS_ + ti * 64 + t0 + r;
            size_t tg = rowbase + ti * 64 + t0 + r;
            float e = expf(cumg[(size_t)(b * NH_ + h) * Ll + tloc]);
            float* yp = y + (tg * NH_ + h) * HD_ + p0;
            float4 yv = *(float4*)yp;
            const float4 xv = *(const float4*)&xbc[tg * CONVD_ + h * HD_ + p0];
            yv.x += acc[r][0] * e + Dh * xv.x;
            yv.y += acc[r][1] * e + Dh * xv.y;
            yv.z += acc[r][2] * e + Dh * xv.z;
            yv.w += acc[r][3] * e + Dh * xv.w;
            *(float4*)yp = yv;
        }
    }
}

// ---------------- gated RMSNorm -> split bf16 ------------------------------
__global__ __launch_bounds__(256) void gated_norm_kernel(
    const float* __restrict__ proj, const float* __restrict__ y,
    const float* __restrict__ nw,
    __nv_bfloat16* __restrict__ gh, __nv_bfloat16* __restrict__ gl)
{
    int row = blockIdx.x;
    int tid = threadIdx.x;
    float gv[16];
    float ss = 0.f;
    const float* yr = y + (size_t)row * INTER_;
    const float* gr = proj + (size_t)row * PROJ_;
#pragma unroll
    for (int k = 0; k < 16; k++) {
        int idx = tid + k * 256;
        float gt = gr[idx];
        float s = 1.f / (1.f + expf(-gt));
        float v = yr[idx] * gt * s;
        gv[k] = v;
        ss = fmaf(v, v, ss);
    }
    __shared__ float red[256];
    red[tid] = ss;
    __syncthreads();
    for (int off = 128; off > 0; off >>= 1) {
        if (tid < off) red[tid] += red[tid + off];
        __syncthreads();
    }
    float scale = rsqrtf(red[0] / (float)INTER_ + 1e-5f);
#pragma unroll
    for (int k = 0; k < 16; k++) {
        int idx = tid + k * 256;
        float o = gv[k] * scale * nw[idx];
        __nv_bfloat16 h = __float2bfloat16(o);
        gh[(size_t)row * INTER_ + idx] = h;
        gl[(size_t)row * INTER_ + idx] = __float2bfloat16(o - __bfloat162float(h));
    }
}

// ---------------- launch ----------------------------------------------------
extern "C" void kernel_launch(void* const* d_in, const int* in_sizes, int n_in,
                              void* d_out, int out_size)
{
    const float* hidden  = (const float*)d_in[0];
    const float* in_w    = (const float*)d_in[1];
    const float* in_b    = (const float*)d_in[2];
    const float* conv_w  = (const float*)d_in[3];
    const float* dt_bias = (const float*)d_in[4];
    const float* A_log   = (const float*)d_in[5];
    const float* Dv      = (const float*)d_in[6];
    const float* norm_w  = (const float*)d_in[7];
    const float* out_w   = (const float*)d_in[8];
    const float* out_b   = (const float*)d_in[9];
    float* out = (float*)d_out;

    float *proj, *xbc, *y, *states, *prev, *cum, *al;
    __nv_bfloat16 *Ah, *Al, *W1h, *W1l, *W2h, *W2l;
    cudaGetSymbolAddress((void**)&proj,   g_proj);
    cudaGetSymbolAddress((void**)&xbc,    g_xbc);
    cudaGetSymbolAddress((void**)&y,      g_y);
    cudaGetSymbolAddress((void**)&states, g_states);
    cudaGetSymbolAddress((void**)&prev,   g_prev);
    cudaGetSymbolAddress((void**)&cum,    g_cum);
    cudaGetSymbolAddress((void**)&al,     g_alast);
    cudaGetSymbolAddress((void**)&Ah,     g_Ah);
    cudaGetSymbolAddress((void**)&Al,     g_Al);
    cudaGetSymbolAddress((void**)&W1h,    g_W1h);
    cudaGetSymbolAddress((void**)&W1l,    g_W1l);
    cudaGetSymbolAddress((void**)&W2h,    g_W2h);
    cudaGetSymbolAddress((void**)&W2l,    g_W2l);

    const int SMEM_INTRA = (128 * 68 * 2 + 64 * 68 * 2 + 512) * 4;
    const int SMEM_OFF   = (64 * 129 + 128 * 68) * 4;
    cudaFuncSetAttribute(scan_intra_kernel,
                         cudaFuncAttributeMaxDynamicSharedMemorySize, SMEM_INTRA);
    cudaFuncSetAttribute(scan_off_kernel,
                         cudaFuncAttributeMaxDynamicSharedMemorySize, SMEM_OFF);
    cudaFuncSetAttribute(tc_gemm_bias,
                         cudaFuncAttributeMaxDynamicSharedMemorySize, GSMEM);

    // 0. split-bf16 conversions
    {
        size_t n4;
        n4 = (size_t)MT * HIDDEN_ / 4;
        cvt_split_kernel<<<(int)((n4 + 255) / 256), 256>>>(
            (const float4*)hidden, (__nv_bfloat162*)Ah, (__nv_bfloat162*)Al, n4, n4);
        size_t n4v = (size_t)PROJ_ * HIDDEN_ / 4, n4t = (size_t)NP1 * HIDDEN_ / 4;
        cvt_split_kernel<<<(int)((n4t + 255) / 256), 256>>>(
            (const float4*)in_w, (__nv_bfloat162*)W1h, (__nv_bfloat162*)W1l, n4v, n4t);
        n4 = (size_t)HIDDEN_ * INTER_ / 4;
        cvt_split_kernel<<<(int)((n4 + 255) / 256), 256>>>(
            (const float4*)out_w, (__nv_bfloat162*)W2h, (__nv_bfloat162*)W2l, n4, n4);
    }

    // 1. in_proj GEMM + bias (tensor cores via mma.sync)
    tc_gemm_bias<<<dim3(NP1 / 128, MT / 128), 256, GSMEM>>>(
        Ah, Al, W1h, W1l, in_b, proj, PROJ_, HIDDEN_);

    // 2. causal depthwise conv + SiLU
    conv_silu_kernel<<<(Bb * Ll * CONVD_ + 255) / 256, 256>>>(proj, conv_w, xbc);

    // 3. intra-chunk scan
    scan_intra_kernel<<<dim3(NH_, NC_, Bb), 256, SMEM_INTRA>>>(
        proj, xbc, dt_bias, A_log, y, states, cum, al);

    // 4. inter-chunk recurrence
    interchunk_kernel<<<Bb * NH_, 256>>>(states, al, prev);

    // 5. inter-chunk output contribution + D skip
    scan_off_kernel<<<dim3(NH_, NC_, Bb), 256, SMEM_OFF>>>(xbc, cum, prev, Dv, y);

    // 6. gated RMSNorm -> split bf16 A for GEMM2
    gated_norm_kernel<<<MT, 256>>>(proj, y, norm_w, Ah, Al);

    // 7. out_proj GEMM + bias (tensor cores via mma.sync)
    tc_gemm_bias<<<dim3(HIDDEN_ / 128, MT / 128), 256, GSMEM>>>(
        Ah, Al, W2h, W2l, out_b, out, HIDDEN_, INTER_);
}

// round 4
// speedup vs baseline: 2.6390x; 1.1655x over previous
#include <cuda_runtime.h>
#include <cuda_bf16.h>
#include <math.h>
#include <cstdint>

#define Bb      2
#define Ll      2048
#define HIDDEN_ 2048
#define PROJ_   8512
#define INTER_  4096
#define CONVD_  4352
#define NH_     64
#define HD_     64
#define ST_     128
#define NC_     8
#define CS_     256
#define MT      (Bb*Ll)      // 4096
#define NP1     8576         // PROJ_ padded to 67*128

// ---------------- static scratch (no allocations allowed) ----------------
__device__ float g_proj  [(size_t)MT*PROJ_];
__device__ float g_xbc   [(size_t)MT*CONVD_];
__device__ float g_y     [(size_t)MT*INTER_];
__device__ float g_states[(size_t)Bb*NC_*NH_*HD_*ST_];
__device__ float g_prev  [(size_t)Bb*NC_*NH_*HD_*ST_];
__device__ float g_cum   [(size_t)Bb*NH_*Ll];
__device__ float g_alast [(size_t)Bb*NH_*NC_];
__device__ float g_P     [(size_t)Bb*NC_*CS_*CS_];      // 4 MB shared C·B^T
__device__ __nv_bfloat16 g_Ah [(size_t)MT*INTER_];
__device__ __nv_bfloat16 g_Al [(size_t)MT*INTER_];
__device__ __nv_bfloat16 g_W1h[(size_t)NP1*HIDDEN_];
__device__ __nv_bfloat16 g_W1l[(size_t)NP1*HIDDEN_];
__device__ __nv_bfloat16 g_W2h[(size_t)HIDDEN_*INTER_];
__device__ __nv_bfloat16 g_W2l[(size_t)HIDDEN_*INTER_];

// ======================= warp-MMA helpers (sm_80 path) ====================
__device__ __forceinline__ uint32_t cvta_smem(const void* p) {
    uint32_t a;
    asm("{ .reg .u64 t; cvta.to.shared.u64 t, %1; cvt.u32.u64 %0, t; }"
        : "=r"(a) : "l"(p));
    return a;
}

__device__ __forceinline__ void ldsm4(uint32_t* r, uint32_t addr) {
    asm volatile("ldmatrix.sync.aligned.m8n8.x4.shared.b16 {%0,%1,%2,%3}, [%4];"
                 : "=r"(r[0]), "=r"(r[1]), "=r"(r[2]), "=r"(r[3]) : "r"(addr));
}

__device__ __forceinline__ void mma16816(float* c, const uint32_t* a,
                                         uint32_t b0, uint32_t b1) {
    asm volatile(
        "mma.sync.aligned.m16n8k16.row.col.f32.bf16.bf16.f32 "
        "{%0,%1,%2,%3}, {%4,%5,%6,%7}, {%8,%9}, {%0,%1,%2,%3};"
        : "+f"(c[0]), "+f"(c[1]), "+f"(c[2]), "+f"(c[3])
        : "r"(a[0]), "r"(a[1]), "r"(a[2]), "r"(a[3]), "r"(b0), "r"(b1));
}

#define CPASYNC16(sa, ga) \
    asm volatile("cp.async.cg.shared.global [%0], [%1], 16;" :: "r"(sa), "l"(ga) : "memory")

#define TILEB  16384u
#define STAGEB 65536u
#define GSMEM  (1024 + 3*65536)

__device__ __forceinline__ void gemm_load_chunk(
    uint32_t tb, int s, int c,
    const __nv_bfloat16* __restrict__ Ah, const __nv_bfloat16* __restrict__ Al,
    const __nv_bfloat16* __restrict__ Wh, const __nv_bfloat16* __restrict__ Wl,
    size_t arow, size_t brow, int K, int tid)
{
    const int seg = tid & 7, r0 = tid >> 3;   // r0: 0..63 (512 threads)
    uint32_t stb = tb + (uint32_t)s * STAGEB;
    size_t ko = ((size_t)c << 6) + (size_t)(seg << 3);
#pragma unroll
    for (int t = 0; t < 2; t++) {
        int r = r0 + 64 * t;
        uint32_t off = (uint32_t)(r * 128 + seg * 16);
        uint32_t so = off ^ ((off >> 3) & 0x70);
        size_t ra = (arow + r) * (size_t)K + ko;
        size_t rb = (brow + r) * (size_t)K + ko;
        CPASYNC16(stb + so,             Ah + ra);
        CPASYNC16(stb + TILEB + so,     Al + ra);
        CPASYNC16(stb + 2*TILEB + so,   Wh + rb);
        CPASYNC16(stb + 3*TILEB + so,   Wl + rb);
    }
    asm volatile("cp.async.commit_group;" ::: "memory");
}

// =========================================================================
// Split-bf16 tensor-core GEMM via mma.sync: C = A*W^T + bias
// 16 warps (512 thr): warp (wm, wn) in 4x4 grid owns 32(M) x 32(N).
// =========================================================================
__global__ __launch_bounds__(512, 1)
void tc_gemm_bias(
    const __nv_bfloat16* __restrict__ Ah, const __nv_bfloat16* __restrict__ Al,
    const __nv_bfloat16* __restrict__ Wh, const __nv_bfloat16* __restrict__ Wl,
    const float* __restrict__ bias, float* __restrict__ C, int N, int K)
{
    extern __shared__ __align__(128) char smem[];
    const int tid = threadIdx.x;
    const int lid = tid & 31, wid = tid >> 5;
    uint32_t sb = cvta_smem(smem);
    uint32_t tb = (sb + 1023u) & ~1023u;

    const size_t arow = (size_t)blockIdx.y * 128;
    const size_t brow = (size_t)blockIdx.x * 128;
    const int NCH = K >> 6;

    const int wm = wid & 3, wn = wid >> 2;
    const int m0 = wm * 32, n0 = wn * 32;
    const int lr  = lid & 15;
    const int lkb = (lid >> 4) * 16;

    float acc[2][4][4];
#pragma unroll
    for (int mi = 0; mi < 2; mi++)
#pragma unroll
        for (int nj = 0; nj < 4; nj++)
#pragma unroll
            for (int q = 0; q < 4; q++) acc[mi][nj][q] = 0.f;

    uint32_t aoff[2], boff[2];
#pragma unroll
    for (int mi = 0; mi < 2; mi++) {
        int row = m0 + mi * 16 + lr;
        aoff[mi] = (uint32_t)(row * 128) + (uint32_t)(((row & 7) * 16) ^ lkb);
    }
#pragma unroll
    for (int ni = 0; ni < 2; ni++) {
        int row = n0 + ni * 16 + lr;
        boff[ni] = (uint32_t)(row * 128) + (uint32_t)(((row & 7) * 16) ^ lkb);
    }

    gemm_load_chunk(tb, 0, 0, Ah, Al, Wh, Wl, arow, brow, K, tid);
    gemm_load_chunk(tb, 1, 1, Ah, Al, Wh, Wl, arow, brow, K, tid);

    for (int c = 0; c < NCH; c++) {
        if (c + 1 < NCH) asm volatile("cp.async.wait_group 1;" ::: "memory");
        else             asm volatile("cp.async.wait_group 0;" ::: "memory");
        __syncthreads();
        if (c + 2 < NCH)
            gemm_load_chunk(tb, (c + 2) % 3, c + 2, Ah, Al, Wh, Wl, arow, brow, K, tid);

        uint32_t stb = tb + (uint32_t)(c % 3) * STAGEB;
#pragma unroll
        for (int kk = 0; kk < 4; kk++) {
            uint32_t kx = (uint32_t)(kk * 32);
            uint32_t a_h[2][4], a_l[2][4];
#pragma unroll
            for (int mi = 0; mi < 2; mi++) {
                uint32_t ad = stb + (aoff[mi] ^ kx);
                ldsm4(a_h[mi], ad);
                ldsm4(a_l[mi], ad + TILEB);
            }
            uint32_t b_h[2][4], b_l[2][4];
#pragma unroll
            for (int ni = 0; ni < 2; ni++) {
                uint32_t bd = stb + (boff[ni] ^ kx);
                ldsm4(b_h[ni], bd + 2*TILEB);
                ldsm4(b_l[ni], bd + 3*TILEB);
            }
#pragma unroll
            for (int mi = 0; mi < 2; mi++)
#pragma unroll
                for (int ni = 0; ni < 2; ni++) {
                    mma16816(acc[mi][2*ni],   a_h[mi], b_h[ni][0], b_h[ni][2]);
                    mma16816(acc[mi][2*ni+1], a_h[mi], b_h[ni][1], b_h[ni][3]);
                    mma16816(acc[mi][2*ni],   a_h[mi], b_l[ni][0], b_l[ni][2]);
                    mma16816(acc[mi][2*ni+1], a_h[mi], b_l[ni][1], b_l[ni][3]);
                    mma16816(acc[mi][2*ni],   a_l[mi], b_h[ni][0], b_h[ni][2]);
                    mma16816(acc[mi][2*ni+1], a_l[mi], b_h[ni][1], b_h[ni][3]);
                }
        }
        __syncthreads();
    }

    const int er = lid >> 2;
    const int ec = (lid & 3) * 2;
#pragma unroll
    for (int mi = 0; mi < 2; mi++) {
        int grow0 = (int)arow + m0 + mi * 16 + er;
#pragma unroll
        for (int nj = 0; nj < 4; nj++) {
            int gcol = (int)brow + n0 + nj * 8 + ec;
            if (gcol + 1 < N) {
                float b0 = __ldg(&bias[gcol]), b1 = __ldg(&bias[gcol + 1]);
                float2 v0 = {acc[mi][nj][0] + b0, acc[mi][nj][1] + b1};
                float2 v1 = {acc[mi][nj][2] + b0, acc[mi][nj][3] + b1};
                *(float2*)&C[(size_t)grow0 * N + gcol] = v0;
                *(float2*)&C[(size_t)(grow0 + 8) * N + gcol] = v1;
            } else if (gcol < N) {
                float b0 = __ldg(&bias[gcol]);
                C[(size_t)grow0 * N + gcol] = acc[mi][nj][0] + b0;
                C[(size_t)(grow0 + 8) * N + gcol] = acc[mi][nj][2] + b0;
            }
        }
    }
}

// ---------------- fp32 -> split bf16 conversion ---------------------------
__global__ void cvt_split_kernel(const float4* __restrict__ src,
                                 __nv_bfloat162* __restrict__ hi,
                                 __nv_bfloat162* __restrict__ lo,
                                 size_t n4v, size_t n4t)
{
    size_t i = (size_t)blockIdx.x * blockDim.x + threadIdx.x;
    size_t stride = (size_t)gridDim.x * blockDim.x;
    for (; i < n4t; i += stride) {
        float4 v = (i < n4v) ? src[i] : make_float4(0.f, 0.f, 0.f, 0.f);
        __nv_bfloat16 h0 = __float2bfloat16(v.x), h1 = __float2bfloat16(v.y);
        __nv_bfloat16 h2 = __float2bfloat16(v.z), h3 = __float2bfloat16(v.w);
        hi[2*i]   = __nv_bfloat162(h0, h1);
        hi[2*i+1] = __nv_bfloat162(h2, h3);
        lo[2*i]   = __nv_bfloat162(__float2bfloat16(v.x - __bfloat162float(h0)),
                                   __float2bfloat16(v.y - __bfloat162float(h1)));
        lo[2*i+1] = __nv_bfloat162(__float2bfloat16(v.z - __bfloat162float(h2)),
                                   __float2bfloat16(v.w - __bfloat162float(h3)));
    }
}

// ---------------- causal depthwise conv (K=4) + SiLU ----------------------
__global__ void conv_silu_kernel(const float* __restrict__ proj,
                                 const float* __restrict__ cw,
                                 float* __restrict__ xbc)
{
    int idx = blockIdx.x * 256 + threadIdx.x;
    if (idx >= Bb * Ll * CONVD_) return;
    int cidx = idx % CONVD_;
    int t = (idx / CONVD_) % Ll;
    int b = idx / (CONVD_ * Ll);
    const float* base = proj + (size_t)(b * Ll) * PROJ_ + INTER_ + cidx;
    float acc = 0.f;
#pragma unroll
    for (int j = 0; j < 4; j++) {
        int tt = t + j - 3;
        if (tt >= 0) acc = fmaf(base[(size_t)tt * PROJ_], cw[cidx * 4 + j], acc);
    }
    float sg = 1.f / (1.f + expf(-acc));
    xbc[idx] = acc * sg;
}

// ---------------- P = C * B^T, shared across heads -------------------------
// pair list: all (i,j) with j <= i (10 lower-triangle 64x64 tiles)
__device__ __constant__ int c_PI[10] = {0,1,1,2,2,2,3,3,3,3};
__device__ __constant__ int c_PJ[10] = {0,0,1,0,1,2,0,1,2,3};

__global__ __launch_bounds__(256, 2) void pmat_kernel(
    const float* __restrict__ xbc, float* __restrict__ P)
{
    const int p = blockIdx.x, c = blockIdx.y, b = blockIdx.z;
    const int i = c_PI[p], j = c_PJ[p];
    const int tid = threadIdx.x;
    extern __shared__ float sm[];
    float* CsT = sm;              // [128][68]
    float* BsT = CsT + 128 * 68;  // [128][68]
    const size_t rowbase = (size_t)(b * Ll + c * CS_);

    for (int idx = tid; idx < 64 * 128; idx += 256) {
        int tl = idx >> 7, n = idx & 127;
        CsT[n * 68 + tl] = xbc[(rowbase + i * 64 + tl) * CONVD_ + (INTER_ + ST_) + n];
        BsT[n * 68 + tl] = xbc[(rowbase + j * 64 + tl) * CONVD_ + INTER_ + n];
    }
    __syncthreads();

    const int tx = tid & 15, ty = tid >> 4;
    const int t0 = ty * 4, s0 = tx * 4;
    float pf[4][4];
#pragma unroll
    for (int r = 0; r < 4; r++)
#pragma unroll
        for (int q = 0; q < 4; q++) pf[r][q] = 0.f;
    for (int n = 0; n < 128; n++) {
        float4 c4 = *(const float4*)&CsT[n * 68 + t0];
        float4 b4 = *(const float4*)&BsT[n * 68 + s0];
        float cr[4] = {c4.x, c4.y, c4.z, c4.w};
        float br[4] = {b4.x, b4.y, b4.z, b4.w};
#pragma unroll
        for (int r = 0; r < 4; r++)
#pragma unroll
            for (int q = 0; q < 4; q++)
                pf[r][q] = fmaf(cr[r], br[q], pf[r][q]);
    }
    float* dst = P + ((size_t)(b * NC_ + c) * CS_) * CS_;
#pragma unroll
    for (int r = 0; r < 4; r++) {
        float4 o = {pf[r][0], pf[r][1], pf[r][2], pf[r][3]};
        *(float4*)&dst[(size_t)(i * 64 + t0 + r) * CS_ + j * 64 + s0] = o;
    }
}

// ---------------- intra-chunk scan: Y_diag + per-chunk states -------------
__global__ __launch_bounds__(256, 2) void scan_intra_kernel(
    const float* __restrict__ proj, const float* __restrict__ xbc,
    const float* __restrict__ gP,
    const float* __restrict__ dt_bias, const float* __restrict__ A_log,
    float* __restrict__ ydiag, float* __restrict__ states,
    float* __restrict__ cumg, float* __restrict__ alast)
{
    const int h = blockIdx.x, c = blockIdx.y, b = blockIdx.z;
    const int tid = threadIdx.x;
    extern __shared__ float sm[];
    float* Ps    = sm;                // [64][68]
    float* xsm   = Ps + 64 * 68;      // [64][68]
    float* BsT   = xsm + 64 * 68;     // [128][68]
    float* dsh   = BsT + 128 * 68;    // [256]
    float* cum   = dsh + 256;         // [256]
    float* wlast = cum + 256;         // [256]
    float* Esh   = wlast + 256;       // [64]
    float* Rsh   = Esh + 64;          // [64]

    {
        float Ah = -expf(A_log[h]);
        float v = proj[(size_t)(b * Ll + c * CS_ + tid) * PROJ_ + (INTER_ + CONVD_) + h]
                + dt_bias[h];
        float dtv = (v > 20.f) ? v : log1pf(expf(v));
        dsh[tid] = dtv;
        cum[tid] = Ah * dtv;
    }
    __syncthreads();
    for (int off = 1; off < 256; off <<= 1) {
        float add = (tid >= off) ? cum[tid - off] : 0.f;
        __syncthreads();
        cum[tid] += add;
        __syncthreads();
    }
    cumg[(size_t)(b * NH_ + h) * Ll + c * CS_ + tid] = cum[tid];
    if (tid == 255) alast[(b * NH_ + h) * NC_ + c] = cum[255];
    wlast[tid] = expf(cum[255] - cum[tid]);   // decay to chunk end (<= 1)
    __syncthreads();

    const int tx = tid & 15, ty = tid >> 4;
    const int t0 = ty * 4, p0 = tx * 4;
    float stacc[4][8];
#pragma unroll
    for (int r = 0; r < 4; r++)
#pragma unroll
        for (int q = 0; q < 8; q++) stacc[r][q] = 0.f;

    const size_t rowbase = (size_t)(b * Ll + c * CS_);
    const float* Pblk = gP + ((size_t)(b * NC_ + c) * CS_) * CS_;

    for (int i = 0; i < 4; i++) {
        // E[t] = exp(cum[64i+t] - cum[64i])  (<= 1, no overflow)
        if (tid < 64) Esh[tid] = expf(cum[i * 64 + tid] - cum[i * 64]);
        float yacc[4][4];
#pragma unroll
        for (int r = 0; r < 4; r++)
#pragma unroll
            for (int q = 0; q < 4; q++) yacc[r][q] = 0.f;

        for (int j = 0; j <= i; j++) {
            __syncthreads();
            for (int idx = tid; idx < 64 * 64; idx += 256) {
                int sl = idx >> 6, p = idx & 63;
                xsm[sl * 68 + p] =
                    xbc[(rowbase + j * 64 + sl) * CONVD_ + h * HD_ + p]
                    * dsh[j * 64 + sl];
            }
            if (j < i && tid < 64)
                Rsh[tid] = expf(cum[i * 64] - cum[j * 64 + tid]);  // <= 1
            if (j == i) {
                for (int idx = tid; idx < 64 * 128; idx += 256) {
                    int sl = idx >> 7, n = idx & 127;
                    BsT[n * 68 + sl] =
                        xbc[(rowbase + j * 64 + sl) * CONVD_ + INTER_ + n];
                }
            }
            __syncthreads();

            if (j == i) {
                // states += B[s]^T * wlast[s] * (x[s]*dt[s])
                int n0 = ty * 8;
                for (int sl = 0; sl < 64; sl++) {
                    float w = wlast[i * 64 + sl];
                    float4 x4 = *(const float4*)&xsm[sl * 68 + p0];
                    float xv[4] = {x4.x * w, x4.y * w, x4.z * w, x4.w * w};
#pragma unroll
                    for (int q = 0; q < 8; q++) {
                        float bv = BsT[(n0 + q) * 68 + sl];
#pragma unroll
                        for (int r = 0; r < 4; r++)
                            stacc[r][q] = fmaf(xv[r], bv, stacc[r][q]);
                    }
                }
                // diagonal tile: elementwise exp with causal mask
                for (int idx = tid; idx < 64 * 64; idx += 256) {
                    int tl = idx >> 6, s = idx & 63;
                    float w = (s <= tl) ? expf(cum[i*64 + tl] - cum[i*64 + s]) : 0.f;
                    Ps[tl * 68 + s] = Pblk[(size_t)(i*64 + tl) * CS_ + j*64 + s] * w;
                }
            } else {
                for (int idx = tid; idx < 64 * 64; idx += 256) {
                    int tl = idx >> 6, s = idx & 63;
                    Ps[tl * 68 + s] = Pblk[(size_t)(i*64 + tl) * CS_ + j*64 + s]
                                      * Esh[tl] * Rsh[s];
                }
            }
            __syncthreads();
            // Y_i += Ps @ (x*dt)
            for (int sl = 0; sl < 64; sl++) {
                float4 x4 = *(const float4*)&xsm[sl * 68 + p0];
#pragma unroll
                for (int r = 0; r < 4; r++) {
                    float pv = Ps[(t0 + r) * 68 + sl];
                    yacc[r][0] = fmaf(pv, x4.x, yacc[r][0]);
                    yacc[r][1] = fmaf(pv, x4.y, yacc[r][1]);
                    yacc[r][2] = fmaf(pv, x4.z, yacc[r][2]);
                    yacc[r][3] = fmaf(pv, x4.w, yacc[r][3]);
                }
            }
        }
        {
#pragma unroll
            for (int r = 0; r < 4; r++) {
                size_t tg = rowbase + i * 64 + t0 + r;
                float4 o = {yacc[r][0], yacc[r][1], yacc[r][2], yacc[r][3]};
                *(float4*)&ydiag[(tg * NH_ + h) * HD_ + p0] = o;
            }
        }
    }
    {
        int n0 = ty * 8;
        size_t base = ((size_t)((b * NC_ + c) * NH_ + h)) * HD_;
#pragma unroll
        for (int r = 0; r < 4; r++) {
            float4 o0 = {stacc[r][0], stacc[r][1], stacc[r][2], stacc[r][3]};
            float4 o1 = {stacc[r][4], stacc[r][5], stacc[r][6], stacc[r][7]};
            float* dst = states + (base + p0 + r) * ST_ + n0;
            *(float4*)dst = o0;
            *(float4*)(dst + 4) = o1;
        }
    }
}

// ---------------- inter-chunk recurrence -----------------------------------
__global__ void interchunk_kernel(const float* __restrict__ states,
                                  const float* __restrict__ alast,
                                  float* __restrict__ prev)
{
    int bh = blockIdx.x;
    int b = bh >> 6, h = bh & 63;
    float dec[NC_];
#pragma unroll
    for (int c = 0; c < NC_; c++)
        dec[c] = expf(alast[(b * NH_ + h) * NC_ + c]);
    for (int e = threadIdx.x; e < HD_ * ST_; e += 256) {
        float run = 0.f;
#pragma unroll
        for (int c = 0; c < NC_; c++) {
            size_t idx = ((size_t)((b * NC_ + c) * NH_ + h)) * (HD_ * ST_) + e;
            prev[idx] = run;
            run = fmaf(run, dec[c] - 1.f, run);
            run = run + states[idx];
        }
    }
}

// ---------------- Y_off + D-skip, accumulate into y ------------------------
__global__ __launch_bounds__(256, 2) void scan_off_kernel(
    const float* __restrict__ xbc, const float* __restrict__ cumg,
    const float* __restrict__ prev, const float* __restrict__ Dv,
    float* __restrict__ y)
{
    const int h = blockIdx.x, c = blockIdx.y, b = blockIdx.z;
    const int tid = threadIdx.x;
    extern __shared__ float sm[];
    float* pvs = sm;                  // [64][129]
    float* CsT = pvs + 64 * 129;      // [128][68]
    float* esh = CsT + 128 * 68;      // [256]
    size_t sbase = ((size_t)((b * NC_ + c) * NH_ + h)) * (HD_ * ST_);
    for (int idx = tid; idx < 64 * 128; idx += 256) {
        int p = idx >> 7, n = idx & 127;
        pvs[p * 129 + n] = prev[sbase + idx];
    }
    esh[tid] = expf(cumg[(size_t)(b * NH_ + h) * Ll + c * CS_ + tid]);
    const float Dh = Dv[h];
    const int tx = tid & 15, ty = tid >> 4;
    const size_t rowbase = (size_t)(b * Ll + c * CS_);
    for (int ti = 0; ti < 4; ti++) {
        __syncthreads();
        for (int idx = tid; idx < 64 * 128; idx += 256) {
            int tl = idx >> 7, n = idx & 127;
            CsT[n * 68 + tl] =
                xbc[(rowbase + ti * 64 + tl) * CONVD_ + (INTER_ + ST_) + n];
        }
        __syncthreads();
        int t0 = ty * 4, p0 = tx * 4;
        float acc[4][4];
#pragma unroll
        for (int r = 0; r < 4; r++)
#pragma unroll
            for (int q = 0; q < 4; q++) acc[r][q] = 0.f;
        for (int n = 0; n < 128; n++) {
            float4 c4 = *(const float4*)&CsT[n * 68 + t0];
            float cr[4] = {c4.x, c4.y, c4.z, c4.w};
            float pv[4];
#pragma unroll
            for (int q = 0; q < 4; q++) pv[q] = pvs[(p0 + q) * 129 + n];
#pragma unroll
            for (int r = 0; r < 4; r++)
#pragma unroll
                for (int q = 0; q < 4; q++)
                    acc[r][q] = fmaf(cr[r], pv[q], acc[r][q]);
        }
#pragma unroll
        for (int r = 0; r < 4; r++) {
            size_t tg = rowbase + ti * 64 + t0 + r;
            float e = esh[ti * 64 + t0 + r];
            float* yp = y + (tg * NH_ + h) * HD_ + p0;
            float4 yv = *(float4*)yp;
            const float4 xv = *(const float4*)&xbc[tg * CONVD_ + h * HD_ + p0];
            yv.x += acc[r][0] * e + Dh * xv.x;
            yv.y += acc[r][1] * e + Dh * xv.y;
            yv.z += acc[r][2] * e + Dh * xv.z;
            yv.w += acc[r][3] * e + Dh * xv.w;
            *(float4*)yp = yv;
        }
    }
}

// ---------------- gated RMSNorm -> split bf16 ------------------------------
__global__ __launch_bounds__(256) void gated_norm_kernel(
    const float* __restrict__ proj, const float* __restrict__ y,
    const float* __restrict__ nw,
    __nv_bfloat16* __restrict__ gh, __nv_bfloat16* __restrict__ gl)
{
    int row = blockIdx.x;
    int tid = threadIdx.x;
    float gv[16];
    float ss = 0.f;
    const float* yr = y + (size_t)row * INTER_;
    const float* gr = proj + (size_t)row * PROJ_;
#pragma unroll
    for (int k = 0; k < 16; k++) {
        int idx = tid + k * 256;
        float gt = gr[idx];
        float s = 1.f / (1.f + expf(-gt));
        float v = yr[idx] * gt * s;
        gv[k] = v;
        ss = fmaf(v, v, ss);
    }
    __shared__ float red[256];
    red[tid] = ss;
    __syncthreads();
    for (int off = 128; off > 0; off >>= 1) {
        if (tid < off) red[tid] += red[tid + off];
        __syncthreads();
    }
    float scale = rsqrtf(red[0] / (float)INTER_ + 1e-5f);
#pragma unroll
    for (int k = 0; k < 16; k++) {
        int idx = tid + k * 256;
        float o = gv[k] * scale * nw[idx];
        __nv_bfloat16 h = __float2bfloat16(o);
        gh[(size_t)row * INTER_ + idx] = h;
        gl[(size_t)row * INTER_ + idx] = __float2bfloat16(o - __bfloat162float(h));
    }
}

// ---------------- launch ----------------------------------------------------
extern "C" void kernel_launch(void* const* d_in, const int* in_sizes, int n_in,
                              void* d_out, int out_size)
{
    const float* hidden  = (const float*)d_in[0];
    const float* in_w    = (const float*)d_in[1];
    const float* in_b    = (const float*)d_in[2];
    const float* conv_w  = (const float*)d_in[3];
    const float* dt_bias = (const float*)d_in[4];
    const float* A_log   = (const float*)d_in[5];
    const float* Dv      = (const float*)d_in[6];
    const float* norm_w  = (const float*)d_in[7];
    const float* out_w   = (const float*)d_in[8];
    const float* out_b   = (const float*)d_in[9];
    float* out = (float*)d_out;

    float *proj, *xbc, *y, *states, *prev, *cum, *al, *Pm;
    __nv_bfloat16 *Ah, *Al, *W1h, *W1l, *W2h, *W2l;
    cudaGetSymbolAddress((void**)&proj,   g_proj);
    cudaGetSymbolAddress((void**)&xbc,    g_xbc);
    cudaGetSymbolAddress((void**)&y,      g_y);
    cudaGetSymbolAddress((void**)&states, g_states);
    cudaGetSymbolAddress((void**)&prev,   g_prev);
    cudaGetSymbolAddress((void**)&cum,    g_cum);
    cudaGetSymbolAddress((void**)&al,     g_alast);
    cudaGetSymbolAddress((void**)&Pm,     g_P);
    cudaGetSymbolAddress((void**)&Ah,     g_Ah);
    cudaGetSymbolAddress((void**)&Al,     g_Al);
    cudaGetSymbolAddress((void**)&W1h,    g_W1h);
    cudaGetSymbolAddress((void**)&W1l,    g_W1l);
    cudaGetSymbolAddress((void**)&W2h,    g_W2h);
    cudaGetSymbolAddress((void**)&W2l,    g_W2l);

    const int SMEM_PMAT  = (128 * 68 * 2) * 4;                        //  69632
    const int SMEM_INTRA = (64*68*2 + 128*68 + 256*3 + 128) * 4;      //  73216
    const int SMEM_OFF   = (64 * 129 + 128 * 68 + 256) * 4;          //  68864
    cudaFuncSetAttribute(pmat_kernel,
                         cudaFuncAttributeMaxDynamicSharedMemorySize, SMEM_PMAT);
    cudaFuncSetAttribute(scan_intra_kernel,
                         cudaFuncAttributeMaxDynamicSharedMemorySize, SMEM_INTRA);
    cudaFuncSetAttribute(scan_off_kernel,
                         cudaFuncAttributeMaxDynamicSharedMemorySize, SMEM_OFF);
    cudaFuncSetAttribute(tc_gemm_bias,
                         cudaFuncAttributeMaxDynamicSharedMemorySize, GSMEM);

    // 0. split-bf16 conversions
    {
        size_t n4;
        n4 = (size_t)MT * HIDDEN_ / 4;
        cvt_split_kernel<<<(int)((n4 + 255) / 256), 256>>>(
            (const float4*)hidden, (__nv_bfloat162*)Ah, (__nv_bfloat162*)Al, n4, n4);
        size_t n4v = (size_t)PROJ_ * HIDDEN_ / 4, n4t = (size_t)NP1 * HIDDEN_ / 4;
        cvt_split_kernel<<<(int)((n4t + 255) / 256), 256>>>(
            (const float4*)in_w, (__nv_bfloat162*)W1h, (__nv_bfloat162*)W1l, n4v, n4t);
        n4 = (size_t)HIDDEN_ * INTER_ / 4;
        cvt_split_kernel<<<(int)((n4 + 255) / 256), 256>>>(
            (const float4*)out_w, (__nv_bfloat162*)W2h, (__nv_bfloat162*)W2l, n4, n4);
    }

    // 1. in_proj GEMM + bias (tensor cores via mma.sync, 512 threads)
    tc_gemm_bias<<<dim3(NP1 / 128, MT / 128), 512, GSMEM>>>(
        Ah, Al, W1h, W1l, in_b, proj, PROJ_, HIDDEN_);

    // 2. causal depthwise conv + SiLU
    conv_silu_kernel<<<(Bb * Ll * CONVD_ + 255) / 256, 256>>>(proj, conv_w, xbc);

    // 2b. shared P = C * B^T per (b, chunk)
    pmat_kernel<<<dim3(10, NC_, Bb), 256, SMEM_PMAT>>>(xbc, Pm);

    // 3. intra-chunk scan (per head, reusing P)
    scan_intra_kernel<<<dim3(NH_, NC_, Bb), 256, SMEM_INTRA>>>(
        proj, xbc, Pm, dt_bias, A_log, y, states, cum, al);

    // 4. inter-chunk recurrence
    interchunk_kernel<<<Bb * NH_, 256>>>(states, al, prev);

    // 5. inter-chunk output contribution + D skip
    scan_off_kernel<<<dim3(NH_, NC_, Bb), 256, SMEM_OFF>>>(xbc, cum, prev, Dv, y);

    // 6. gated RMSNorm -> split bf16 A for GEMM2
    gated_norm_kernel<<<MT, 256>>>(proj, y, norm_w, Ah, Al);

    // 7. out_proj GEMM + bias (tensor cores via mma.sync, 512 threads)
    tc_gemm_bias<<<dim3(HIDDEN_ / 128, MT / 128), 512, GSMEM>>>(
        Ah, Al, W2h, W2l, out_b, out, HIDDEN_, INTER_);
}

// round 5
// speedup vs baseline: 3.3082x; 1.2536x over previous
#include <cuda_runtime.h>
#include <cuda_bf16.h>
#include <cuda_fp16.h>
#include <math.h>
#include <cstdint>

#define Bb      2
#define Ll      2048
#define HIDDEN_ 2048
#define PROJ_   8512
#define INTER_  4096
#define CONVD_  4352
#define NH_     64
#define HD_     64
#define ST_     128
#define NC_     8
#define CS_     256
#define MT      (Bb*Ll)      // 4096
#define NP1     8576         // PROJ_ padded to 67*128

#define RES_SCALE 2048.f
#define RES_INV   (1.f/2048.f)

// ---------------- static scratch (no allocations allowed) ----------------
__device__ float g_proj  [(size_t)MT*PROJ_];
__device__ float g_xbc   [(size_t)MT*CONVD_];
__device__ float g_y     [(size_t)MT*INTER_];
__device__ float g_states[(size_t)Bb*NC_*NH_*HD_*ST_];
__device__ float g_prev  [(size_t)Bb*NC_*NH_*HD_*ST_];
__device__ float g_cum   [(size_t)Bb*NH_*Ll];
__device__ float g_alast [(size_t)Bb*NH_*NC_];
__device__ float g_P     [(size_t)Bb*NC_*CS_*CS_];      // 4 MB shared C·B^T
__device__ __half g_Af [(size_t)MT*INTER_];              // fp16 activations (reused)
__device__ __half g_W1h[(size_t)NP1*HIDDEN_];
__device__ __half g_W1l[(size_t)NP1*HIDDEN_];
__device__ __half g_W2h[(size_t)HIDDEN_*INTER_];
__device__ __half g_W2l[(size_t)HIDDEN_*INTER_];

// ======================= warp-MMA helpers (sm_80 path) ====================
__device__ __forceinline__ uint32_t cvta_smem(const void* p) {
    uint32_t a;
    asm("{ .reg .u64 t; cvta.to.shared.u64 t, %1; cvt.u32.u64 %0, t; }"
        : "=r"(a) : "l"(p));
    return a;
}

__device__ __forceinline__ void ldsm4(uint32_t* r, uint32_t addr) {
    asm volatile("ldmatrix.sync.aligned.m8n8.x4.shared.b16 {%0,%1,%2,%3}, [%4];"
                 : "=r"(r[0]), "=r"(r[1]), "=r"(r[2]), "=r"(r[3]) : "r"(addr));
}

// fp16 in, fp32 accumulate
__device__ __forceinline__ void mma16816(float* c, const uint32_t* a,
                                         uint32_t b0, uint32_t b1) {
    asm volatile(
        "mma.sync.aligned.m16n8k16.row.col.f32.f16.f16.f32 "
        "{%0,%1,%2,%3}, {%4,%5,%6,%7}, {%8,%9}, {%0,%1,%2,%3};"
        : "+f"(c[0]), "+f"(c[1]), "+f"(c[2]), "+f"(c[3])
        : "r"(a[0]), "r"(a[1]), "r"(a[2]), "r"(a[3]), "r"(b0), "r"(b1));
}

// fp16 in, fp16 accumulate (2 packed regs)
__device__ __forceinline__ void mma16816h(uint32_t* c, const uint32_t* a,
                                          uint32_t b0, uint32_t b1) {
    asm volatile(
        "mma.sync.aligned.m16n8k16.row.col.f16.f16.f16.f16 "
        "{%0,%1}, {%2,%3,%4,%5}, {%6,%7}, {%0,%1};"
        : "+r"(c[0]), "+r"(c[1])
        : "r"(a[0]), "r"(a[1]), "r"(a[2]), "r"(a[3]), "r"(b0), "r"(b1));
}

#define CPASYNC16(sa, ga) \
    asm volatile("cp.async.cg.shared.global [%0], [%1], 16;" :: "r"(sa), "l"(ga) : "memory")

#define TILEB  16384u
#define STAGEB 49152u
#define NSTG   4
#define GSMEM  (1024 + NSTG*49152)   // 197632

__device__ __forceinline__ void gemm_load_chunk(
    uint32_t tb, int s, int c,
    const __half* __restrict__ A,
    const __half* __restrict__ Wh, const __half* __restrict__ Wl,
    size_t arow, size_t brow, int K, int tid)
{
    const int seg = tid & 7, r0 = tid >> 3;   // r0: 0..63 (512 threads)
    uint32_t stb = tb + (uint32_t)s * STAGEB;
    size_t ko = ((size_t)c << 6) + (size_t)(seg << 3);
#pragma unroll
    for (int t = 0; t < 2; t++) {
        int r = r0 + 64 * t;
        uint32_t off = (uint32_t)(r * 128 + seg * 16);
        uint32_t so = off ^ ((off >> 3) & 0x70);
        size_t ra = (arow + r) * (size_t)K + ko;
        size_t rb = (brow + r) * (size_t)K + ko;
        CPASYNC16(stb + so,             A  + ra);
        CPASYNC16(stb + TILEB + so,     Wh + rb);
        CPASYNC16(stb + 2*TILEB + so,   Wl + rb);
    }
    asm volatile("cp.async.commit_group;" ::: "memory");
}

// =========================================================================
// 2-pass fp16 tensor-core GEMM: C = A*(Wh + Wl/2048)^T + bias
// 16 warps (512 thr): warp (wm, wn) in 4x4 grid owns 32(M) x 32(N).
// acc1: f32 (A*Wh), acc2: f16 (A*Wl, scaled residual).
// =========================================================================
__global__ __launch_bounds__(512, 1)
void tc_gemm_bias(
    const __half* __restrict__ A,
    const __half* __restrict__ Wh, const __half* __restrict__ Wl,
    const float* __restrict__ bias, float* __restrict__ C, int N, int K)
{
    extern __shared__ __align__(128) char smem[];
    const int tid = threadIdx.x;
    const int lid = tid & 31, wid = tid >> 5;
    uint32_t sb = cvta_smem(smem);
    uint32_t tb = (sb + 1023u) & ~1023u;

    const size_t arow = (size_t)blockIdx.y * 128;
    const size_t brow = (size_t)blockIdx.x * 128;
    const int NCH = K >> 6;

    const int wm = wid & 3, wn = wid >> 2;
    const int m0 = wm * 32, n0 = wn * 32;
    const int lr  = lid & 15;
    const int lkb = (lid >> 4) * 16;

    float acc1[2][4][4];
    uint32_t acc2[2][4][2];
#pragma unroll
    for (int mi = 0; mi < 2; mi++)
#pragma unroll
        for (int nj = 0; nj < 4; nj++) {
#pragma unroll
            for (int q = 0; q < 4; q++) acc1[mi][nj][q] = 0.f;
            acc2[mi][nj][0] = 0u; acc2[mi][nj][1] = 0u;
        }

    uint32_t aoff[2], boff[2];
#pragma unroll
    for (int mi = 0; mi < 2; mi++) {
        int row = m0 + mi * 16 + lr;
        aoff[mi] = (uint32_t)(row * 128) + (uint32_t)(((row & 7) * 16) ^ lkb);
    }
#pragma unroll
    for (int ni = 0; ni < 2; ni++) {
        int row = n0 + ni * 16 + lr;
        boff[ni] = (uint32_t)(row * 128) + (uint32_t)(((row & 7) * 16) ^ lkb);
    }

    gemm_load_chunk(tb, 0, 0, A, Wh, Wl, arow, brow, K, tid);
    gemm_load_chunk(tb, 1, 1, A, Wh, Wl, arow, brow, K, tid);
    gemm_load_chunk(tb, 2, 2, A, Wh, Wl, arow, brow, K, tid);

    for (int c = 0; c < NCH; c++) {
        if (c + 1 < NCH) asm volatile("cp.async.wait_group 2;" ::: "memory");
        else             asm volatile("cp.async.wait_group 0;" ::: "memory");
        __syncthreads();
        if (c + 3 < NCH)
            gemm_load_chunk(tb, (c + 3) % NSTG, c + 3, A, Wh, Wl, arow, brow, K, tid);

        uint32_t stb = tb + (uint32_t)(c % NSTG) * STAGEB;
#pragma unroll
        for (int kk = 0; kk < 4; kk++) {
            uint32_t kx = (uint32_t)(kk * 32);
            uint32_t a_f[2][4];
#pragma unroll
            for (int mi = 0; mi < 2; mi++)
                ldsm4(a_f[mi], stb + (aoff[mi] ^ kx));
            uint32_t w_h[2][4], w_l[2][4];
#pragma unroll
            for (int ni = 0; ni < 2; ni++) {
                uint32_t bd = stb + (boff[ni] ^ kx);
                ldsm4(w_h[ni], bd + TILEB);
                ldsm4(w_l[ni], bd + 2*TILEB);
            }
#pragma unroll
            for (int mi = 0; mi < 2; mi++)
#pragma unroll
                for (int ni = 0; ni < 2; ni++) {
                    mma16816(acc1[mi][2*ni],    a_f[mi], w_h[ni][0], w_h[ni][2]);
                    mma16816(acc1[mi][2*ni+1],  a_f[mi], w_h[ni][1], w_h[ni][3]);
                    mma16816h(acc2[mi][2*ni],   a_f[mi], w_l[ni][0], w_l[ni][2]);
                    mma16816h(acc2[mi][2*ni+1], a_f[mi], w_l[ni][1], w_l[ni][3]);
                }
        }
        __syncthreads();
    }

    const int er = lid >> 2;
    const int ec = (lid & 3) * 2;
#pragma unroll
    for (int mi = 0; mi < 2; mi++) {
        int grow0 = (int)arow + m0 + mi * 16 + er;
#pragma unroll
        for (int nj = 0; nj < 4; nj++) {
            int gcol = (int)brow + n0 + nj * 8 + ec;
            float2 l0 = __half22float2(*(const __half2*)&acc2[mi][nj][0]);
            float2 l1 = __half22float2(*(const __half2*)&acc2[mi][nj][1]);
            if (gcol + 1 < N) {
                float b0 = __ldg(&bias[gcol]), b1 = __ldg(&bias[gcol + 1]);
                float2 v0 = {acc1[mi][nj][0] + l0.x * RES_INV + b0,
                             acc1[mi][nj][1] + l0.y * RES_INV + b1};
                float2 v1 = {acc1[mi][nj][2] + l1.x * RES_INV + b0,
                             acc1[mi][nj][3] + l1.y * RES_INV + b1};
                *(float2*)&C[(size_t)grow0 * N + gcol] = v0;
                *(float2*)&C[(size_t)(grow0 + 8) * N + gcol] = v1;
            } else if (gcol < N) {
                float b0 = __ldg(&bias[gcol]);
                C[(size_t)grow0 * N + gcol] = acc1[mi][nj][0] + l0.x * RES_INV + b0;
                C[(size_t)(grow0 + 8) * N + gcol] = acc1[mi][nj][2] + l1.x * RES_INV + b0;
            }
        }
    }
}

// ---------------- fp32 -> fp16 conversions ---------------------------------
__global__ void cvt_fp16_kernel(const float4* __restrict__ src,
                                __half2* __restrict__ dst, size_t n4)
{
    size_t i = (size_t)blockIdx.x * blockDim.x + threadIdx.x;
    if (i >= n4) return;
    float4 v = src[i];
    dst[2*i]   = __floats2half2_rn(v.x, v.y);
    dst[2*i+1] = __floats2half2_rn(v.z, v.w);
}

__global__ void cvt_split_fp16_kernel(const float4* __restrict__ src,
                                      __half2* __restrict__ hi,
                                      __half2* __restrict__ lo,
                                      size_t n4v, size_t n4t)
{
    size_t i = (size_t)blockIdx.x * blockDim.x + threadIdx.x;
    if (i >= n4t) return;
    float4 v = (i < n4v) ? src[i] : make_float4(0.f, 0.f, 0.f, 0.f);
    __half h0 = __float2half_rn(v.x), h1 = __float2half_rn(v.y);
    __half h2 = __float2half_rn(v.z), h3 = __float2half_rn(v.w);
    hi[2*i]   = __halves2half2(h0, h1);
    hi[2*i+1] = __halves2half2(h2, h3);
    lo[2*i]   = __floats2half2_rn((v.x - __half2float(h0)) * RES_SCALE,
                                  (v.y - __half2float(h1)) * RES_SCALE);
    lo[2*i+1] = __floats2half2_rn((v.z - __half2float(h2)) * RES_SCALE,
                                  (v.w - __half2float(h3)) * RES_SCALE);
}

// ---------------- causal depthwise conv (K=4) + SiLU ----------------------
__global__ void conv_silu_kernel(const float* __restrict__ proj,
                                 const float* __restrict__ cw,
                                 float* __restrict__ xbc)
{
    int idx = blockIdx.x * 256 + threadIdx.x;
    if (idx >= Bb * Ll * CONVD_) return;
    int cidx = idx % CONVD_;
    int t = (idx / CONVD_) % Ll;
    int b = idx / (CONVD_ * Ll);
    const float* base = proj + (size_t)(b * Ll) * PROJ_ + INTER_ + cidx;
    float acc = 0.f;
#pragma unroll
    for (int j = 0; j < 4; j++) {
        int tt = t + j - 3;
        if (tt >= 0) acc = fmaf(base[(size_t)tt * PROJ_], cw[cidx * 4 + j], acc);
    }
    float sg = 1.f / (1.f + expf(-acc));
    xbc[idx] = acc * sg;
}

// ---------------- P = C * B^T, shared across heads -------------------------
__device__ __constant__ int c_PI[10] = {0,1,1,2,2,2,3,3,3,3};
__device__ __constant__ int c_PJ[10] = {0,0,1,0,1,2,0,1,2,3};

__global__ __launch_bounds__(256, 2) void pmat_kernel(
    const float* __restrict__ xbc, float* __restrict__ P)
{
    const int p = blockIdx.x, c = blockIdx.y, b = blockIdx.z;
    const int i = c_PI[p], j = c_PJ[p];
    const int tid = threadIdx.x;
    extern __shared__ float sm[];
    float* CsT = sm;              // [128][68]
    float* BsT = CsT + 128 * 68;  // [128][68]
    const size_t rowbase = (size_t)(b * Ll + c * CS_);

    for (int idx = tid; idx < 64 * 128; idx += 256) {
        int tl = idx >> 7, n = idx & 127;
        CsT[n * 68 + tl] = xbc[(rowbase + i * 64 + tl) * CONVD_ + (INTER_ + ST_) + n];
        BsT[n * 68 + tl] = xbc[(rowbase + j * 64 + tl) * CONVD_ + INTER_ + n];
    }
    __syncthreads();

    const int tx = tid & 15, ty = tid >> 4;
    const int t0 = ty * 4, s0 = tx * 4;
    float pf[4][4];
#pragma unroll
    for (int r = 0; r < 4; r++)
#pragma unroll
        for (int q = 0; q < 4; q++) pf[r][q] = 0.f;
    for (int n = 0; n < 128; n++) {
        float4 c4 = *(const float4*)&CsT[n * 68 + t0];
        float4 b4 = *(const float4*)&BsT[n * 68 + s0];
        float cr[4] = {c4.x, c4.y, c4.z, c4.w};
        float br[4] = {b4.x, b4.y, b4.z, b4.w};
#pragma unroll
        for (int r = 0; r < 4; r++)
#pragma unroll
            for (int q = 0; q < 4; q++)
                pf[r][q] = fmaf(cr[r], br[q], pf[r][q]);
    }
    float* dst = P + ((size_t)(b * NC_ + c) * CS_) * CS_;
#pragma unroll
    for (int r = 0; r < 4; r++) {
        float4 o = {pf[r][0], pf[r][1], pf[r][2], pf[r][3]};
        *(float4*)&dst[(size_t)(i * 64 + t0 + r) * CS_ + j * 64 + s0] = o;
    }
}

// ---------------- intra-chunk scan: Y_diag + per-chunk states -------------
__global__ __launch_bounds__(256, 2) void scan_intra_kernel(
    const float* __restrict__ proj, const float* __restrict__ xbc,
    const float* __restrict__ gP,
    const float* __restrict__ dt_bias, const float* __restrict__ A_log,
    float* __restrict__ ydiag, float* __restrict__ states,
    float* __restrict__ cumg, float* __restrict__ alast)
{
    const int h = blockIdx.x, c = blockIdx.y, b = blockIdx.z;
    const int tid = threadIdx.x;
    extern __shared__ float sm[];
    float* Ps    = sm;                // [64][68]
    float* xsm   = Ps + 64 * 68;      // [64][68]
    float* BsT   = xsm + 64 * 68;     // [128][68]
    float* dsh   = BsT + 128 * 68;    // [256]
    float* cum   = dsh + 256;         // [256]
    float* wlast = cum + 256;         // [256]
    float* Esh   = wlast + 256;       // [64]
    float* Rsh   = Esh + 64;          // [64]

    {
        float Ah = -expf(A_log[h]);
        float v = proj[(size_t)(b * Ll + c * CS_ + tid) * PROJ_ + (INTER_ + CONVD_) + h]
                + dt_bias[h];
        float dtv = (v > 20.f) ? v : log1pf(expf(v));
        dsh[tid] = dtv;
        cum[tid] = Ah * dtv;
    }
    __syncthreads();
    for (int off = 1; off < 256; off <<= 1) {
        float add = (tid >= off) ? cum[tid - off] : 0.f;
        __syncthreads();
        cum[tid] += add;
        __syncthreads();
    }
    cumg[(size_t)(b * NH_ + h) * Ll + c * CS_ + tid] = cum[tid];
    if (tid == 255) alast[(b * NH_ + h) * NC_ + c] = cum[255];
    wlast[tid] = expf(cum[255] - cum[tid]);
    __syncthreads();

    const int tx = tid & 15, ty = tid >> 4;
    const int t0 = ty * 4, p0 = tx * 4;
    float stacc[4][8];
#pragma unroll
    for (int r = 0; r < 4; r++)
#pragma unroll
        for (int q = 0; q < 8; q++) stacc[r][q] = 0.f;

    const size_t rowbase = (size_t)(b * Ll + c * CS_);
    const float* Pblk = gP + ((size_t)(b * NC_ + c) * CS_) * CS_;

    for (int i = 0; i < 4; i++) {
        if (tid < 64) Esh[tid] = expf(cum[i * 64 + tid] - cum[i * 64]);
        float yacc[4][4];
#pragma unroll
        for (int r = 0; r < 4; r++)
#pragma unroll
            for (int q = 0; q < 4; q++) yacc[r][q] = 0.f;

        for (int j = 0; j <= i; j++) {
            __syncthreads();
            for (int idx = tid; idx < 64 * 64; idx += 256) {
                int sl = idx >> 6, p = idx & 63;
                xsm[sl * 68 + p] =
                    xbc[(rowbase + j * 64 + sl) * CONVD_ + h * HD_ + p]
                    * dsh[j * 64 + sl];
            }
            if (j < i && tid < 64)
                Rsh[tid] = expf(cum[i * 64] - cum[j * 64 + tid]);
            if (j == i) {
                for (int idx = tid; idx < 64 * 128; idx += 256) {
                    int sl = idx >> 7, n = idx & 127;
                    BsT[n * 68 + sl] =
                        xbc[(rowbase + j * 64 + sl) * CONVD_ + INTER_ + n];
                }
            }
            __syncthreads();

            if (j == i) {
                int n0 = ty * 8;
                for (int sl = 0; sl < 64; sl++) {
                    float w = wlast[i * 64 + sl];
                    float4 x4 = *(const float4*)&xsm[sl * 68 + p0];
                    float xv[4] = {x4.x * w, x4.y * w, x4.z * w, x4.w * w};
#pragma unroll
                    for (int q = 0; q < 8; q++) {
                        float bv = BsT[(n0 + q) * 68 + sl];
#pragma unroll
                        for (int r = 0; r < 4; r++)
                            stacc[r][q] = fmaf(xv[r], bv, stacc[r][q]);
                    }
                }
                for (int idx = tid; idx < 64 * 64; idx += 256) {
                    int tl = idx >> 6, s = idx & 63;
                    float w = (s <= tl) ? expf(cum[i*64 + tl] - cum[i*64 + s]) : 0.f;
                    Ps[tl * 68 + s] = Pblk[(size_t)(i*64 + tl) * CS_ + j*64 + s] * w;
                }
            } else {
                for (int idx = tid; idx < 64 * 64; idx += 256) {
                    int tl = idx >> 6, s = idx & 63;
                    Ps[tl * 68 + s] = Pblk[(size_t)(i*64 + tl) * CS_ + j*64 + s]
                                      * Esh[tl] * Rsh[s];
                }
            }
            __syncthreads();
            for (int sl = 0; sl < 64; sl++) {
                float4 x4 = *(const float4*)&xsm[sl * 68 + p0];
#pragma unroll
                for (int r = 0; r < 4; r++) {
                    float pv = Ps[(t0 + r) * 68 + sl];
                    yacc[r][0] = fmaf(pv, x4.x, yacc[r][0]);
                    yacc[r][1] = fmaf(pv, x4.y, yacc[r][1]);
                    yacc[r][2] = fmaf(pv, x4.z, yacc[r][2]);
                    yacc[r][3] = fmaf(pv, x4.w, yacc[r][3]);
                }
            }
        }
        {
#pragma unroll
            for (int r = 0; r < 4; r++) {
                size_t tg = rowbase + i * 64 + t0 + r;
                float4 o = {yacc[r][0], yacc[r][1], yacc[r][2], yacc[r][3]};
                *(float4*)&ydiag[(tg * NH_ + h) * HD_ + p0] = o;
            }
        }
    }
    {
        int n0 = ty * 8;
        size_t base = ((size_t)((b * NC_ + c) * NH_ + h)) * HD_;
#pragma unroll
        for (int r = 0; r < 4; r++) {
            float4 o0 = {stacc[r][0], stacc[r][1], stacc[r][2], stacc[r][3]};
            float4 o1 = {stacc[r][4], stacc[r][5], stacc[r][6], stacc[r][7]};
            float* dst = states + (base + p0 + r) * ST_ + n0;
            *(float4*)dst = o0;
            *(float4*)(dst + 4) = o1;
        }
    }
}

// ---------------- inter-chunk recurrence -----------------------------------
__global__ void interchunk_kernel(const float* __restrict__ states,
                                  const float* __restrict__ alast,
                                  float* __restrict__ prev)
{
    int bh = blockIdx.x;
    int b = bh >> 6, h = bh & 63;
    float dec[NC_];
#pragma unroll
    for (int c = 0; c < NC_; c++)
        dec[c] = expf(alast[(b * NH_ + h) * NC_ + c]);
    for (int e = threadIdx.x; e < HD_ * ST_; e += 256) {
        float run = 0.f;
#pragma unroll
        for (int c = 0; c < NC_; c++) {
            size_t idx = ((size_t)((b * NC_ + c) * NH_ + h)) * (HD_ * ST_) + e;
            prev[idx] = run;
            run = fmaf(run, dec[c] - 1.f, run);
            run = run + states[idx];
        }
    }
}

// ---------------- Y_off + D-skip, accumulate into y ------------------------
__global__ __launch_bounds__(256, 2) void scan_off_kernel(
    const float* __restrict__ xbc, const float* __restrict__ cumg,
    const float* __restrict__ prev, const float* __restrict__ Dv,
    float* __restrict__ y)
{
    const int h = blockIdx.x, c = blockIdx.y, b = blockIdx.z;
    const int tid = threadIdx.x;
    extern __shared__ float sm[];
    float* pvs = sm;                  // [64][129]
    float* CsT = pvs + 64 * 129;      // [128][68]
    float* esh = CsT + 128 * 68;      // [256]
    size_t sbase = ((size_t)((b * NC_ + c) * NH_ + h)) * (HD_ * ST_);
    for (int idx = tid; idx < 64 * 128; idx += 256) {
        int p = idx >> 7, n = idx & 127;
        pvs[p * 129 + n] = prev[sbase + idx];
    }
    esh[tid] = expf(cumg[(size_t)(b * NH_ + h) * Ll + c * CS_ + tid]);
    const float Dh = Dv[h];
    const int tx = tid & 15, ty = tid >> 4;
    const size_t rowbase = (size_t)(b * Ll + c * CS_);
    for (int ti = 0; ti < 4; ti++) {
        __syncthreads();
        for (int idx = tid; idx < 64 * 128; idx += 256) {
            int tl = idx >> 7, n = idx & 127;
            CsT[n * 68 + tl] =
                xbc[(rowbase + ti * 64 + tl) * CONVD_ + (INTER_ + ST_) + n];
        }
        __syncthreads();
        int t0 = ty * 4, p0 = tx * 4;
        float acc[4][4];
#pragma unroll
        for (int r = 0; r < 4; r++)
#pragma unroll
            for (int q = 0; q < 4; q++) acc[r][q] = 0.f;
        for (int n = 0; n < 128; n++) {
            float4 c4 = *(const float4*)&CsT[n * 68 + t0];
            float cr[4] = {c4.x, c4.y, c4.z, c4.w};
            float pv[4];
#pragma unroll
            for (int q = 0; q < 4; q++) pv[q] = pvs[(p0 + q) * 129 + n];
#pragma unroll
            for (int r = 0; r < 4; r++)
#pragma unroll
                for (int q = 0; q < 4; q++)
                    acc[r][q] = fmaf(cr[r], pv[q], acc[r][q]);
        }
#pragma unroll
        for (int r = 0; r < 4; r++) {
            size_t tg = rowbase + ti * 64 + t0 + r;
            float e = esh[ti * 64 + t0 + r];
            float* yp = y + (tg * NH_ + h) * HD_ + p0;
            float4 yv = *(float4*)yp;
            const float4 xv = *(const float4*)&xbc[tg * CONVD_ + h * HD_ + p0];
            yv.x += acc[r][0] * e + Dh * xv.x;
            yv.y += acc[r][1] * e + Dh * xv.y;
            yv.z += acc[r][2] * e + Dh * xv.z;
            yv.w += acc[r][3] * e + Dh * xv.w;
            *(float4*)yp = yv;
        }
    }
}

// ---------------- gated RMSNorm -> fp16 A for GEMM2 ------------------------
__global__ __launch_bounds__(256) void gated_norm_kernel(
    const float* __restrict__ proj, const float* __restrict__ y,
    const float* __restrict__ nw, __half* __restrict__ gf)
{
    int row = blockIdx.x;
    int tid = threadIdx.x;
    float gv[16];
    float ss = 0.f;
    const float* yr = y + (size_t)row * INTER_;
    const float* gr = proj + (size_t)row * PROJ_;
#pragma unroll
    for (int k = 0; k < 16; k++) {
        int idx = tid + k * 256;
        float gt = gr[idx];
        float s = 1.f / (1.f + expf(-gt));
        float v = yr[idx] * gt * s;
        gv[k] = v;
        ss = fmaf(v, v, ss);
    }
    __shared__ float red[256];
    red[tid] = ss;
    __syncthreads();
    for (int off = 128; off > 0; off >>= 1) {
        if (tid < off) red[tid] += red[tid + off];
        __syncthreads();
    }
    float scale = rsqrtf(red[0] / (float)INTER_ + 1e-5f);
#pragma unroll
    for (int k = 0; k < 16; k++) {
        int idx = tid + k * 256;
        gf[(size_t)row * INTER_ + idx] = __float2half_rn(gv[k] * scale * nw[idx]);
    }
}

// ---------------- launch ----------------------------------------------------
extern "C" void kernel_launch(void* const* d_in, const int* in_sizes, int n_in,
                              void* d_out, int out_size)
{
    const float* hidden  = (const float*)d_in[0];
    const float* in_w    = (const float*)d_in[1];
    const float* in_b    = (const float*)d_in[2];
    const float* conv_w  = (const float*)d_in[3];
    const float* dt_bias = (const float*)d_in[4];
    const float* A_log   = (const float*)d_in[5];
    const float* Dv      = (const float*)d_in[6];
    const float* norm_w  = (const float*)d_in[7];
    const float* out_w   = (const float*)d_in[8];
    const float* out_b   = (const float*)d_in[9];
    float* out = (float*)d_out;

    float *proj, *xbc, *y, *states, *prev, *cum, *al, *Pm;
    __half *Af, *W1h, *W1l, *W2h, *W2l;
    cudaGetSymbolAddress((void**)&proj,   g_proj);
    cudaGetSymbolAddress((void**)&xbc,    g_xbc);
    cudaGetSymbolAddress((void**)&y,      g_y);
    cudaGetSymbolAddress((void**)&states, g_states);
    cudaGetSymbolAddress((void**)&prev,   g_prev);
    cudaGetSymbolAddress((void**)&cum,    g_cum);
    cudaGetSymbolAddress((void**)&al,     g_alast);
    cudaGetSymbolAddress((void**)&Pm,     g_P);
    cudaGetSymbolAddress((void**)&Af,     g_Af);
    cudaGetSymbolAddress((void**)&W1h,    g_W1h);
    cudaGetSymbolAddress((void**)&W1l,    g_W1l);
    cudaGetSymbolAddress((void**)&W2h,    g_W2h);
    cudaGetSymbolAddress((void**)&W2l,    g_W2l);

    const int SMEM_PMAT  = (128 * 68 * 2) * 4;
    const int SMEM_INTRA = (64*68*2 + 128*68 + 256*3 + 128) * 4;
    const int SMEM_OFF   = (64 * 129 + 128 * 68 + 256) * 4;
    cudaFuncSetAttribute(pmat_kernel,
                         cudaFuncAttributeMaxDynamicSharedMemorySize, SMEM_PMAT);
    cudaFuncSetAttribute(scan_intra_kernel,
                         cudaFuncAttributeMaxDynamicSharedMemorySize, SMEM_INTRA);
    cudaFuncSetAttribute(scan_off_kernel,
                         cudaFuncAttributeMaxDynamicSharedMemorySize, SMEM_OFF);
    cudaFuncSetAttribute(tc_gemm_bias,
                         cudaFuncAttributeMaxDynamicSharedMemorySize, GSMEM);

    // 0. fp16 conversions
    {
        size_t n4 = (size_t)MT * HIDDEN_ / 4;
        cvt_fp16_kernel<<<(int)((n4 + 255) / 256), 256>>>(
            (const float4*)hidden, (__half2*)Af, n4);
        size_t n4v = (size_t)PROJ_ * HIDDEN_ / 4, n4t = (size_t)NP1 * HIDDEN_ / 4;
        cvt_split_fp16_kernel<<<(int)((n4t + 255) / 256), 256>>>(
            (const float4*)in_w, (__half2*)W1h, (__half2*)W1l, n4v, n4t);
        n4 = (size_t)HIDDEN_ * INTER_ / 4;
        cvt_split_fp16_kernel<<<(int)((n4 + 255) / 256), 256>>>(
            (const float4*)out_w, (__half2*)W2h, (__half2*)W2l, n4, n4);
    }

    // 1. in_proj GEMM + bias (2-pass fp16 mma.sync)
    tc_gemm_bias<<<dim3(NP1 / 128, MT / 128), 512, GSMEM>>>(
        Af, W1h, W1l, in_b, proj, PROJ_, HIDDEN_);

    // 2. causal depthwise conv + SiLU
    conv_silu_kernel<<<(Bb * Ll * CONVD_ + 255) / 256, 256>>>(proj, conv_w, xbc);

    // 2b. shared P = C * B^T per (b, chunk)
    pmat_kernel<<<dim3(10, NC_, Bb), 256, SMEM_PMAT>>>(xbc, Pm);

    // 3. intra-chunk scan (per head, reusing P)
    scan_intra_kernel<<<dim3(NH_, NC_, Bb), 256, SMEM_INTRA>>>(
        proj, xbc, Pm, dt_bias, A_log, y, states, cum, al);

    // 4. inter-chunk recurrence
    interchunk_kernel<<<Bb * NH_, 256>>>(states, al, prev);

    // 5. inter-chunk output contribution + D skip
    scan_off_kernel<<<dim3(NH_, NC_, Bb), 256, SMEM_OFF>>>(xbc, cum, prev, Dv, y);

    // 6. gated RMSNorm -> fp16 A for GEMM2 (reuses Af)
    gated_norm_kernel<<<MT, 256>>>(proj, y, norm_w, Af);

    // 7. out_proj GEMM + bias (2-pass fp16 mma.sync)
    tc_gemm_bias<<<dim3(HIDDEN_ / 128, MT / 128), 512, GSMEM>>>(
        Af, W2h, W2l, out_b, out, HIDDEN_, INTER_);
}

// round 6
// speedup vs baseline: 3.4449x; 1.0413x over previous
#include <cuda_runtime.h>
#include <cuda_bf16.h>
#include <cuda_fp16.h>
#include <math.h>
#include <cstdint>

#define Bb      2
#define Ll      2048
#define HIDDEN_ 2048
#define PROJ_   8512
#define INTER_  4096
#define CONVD_  4352
#define NH_     64
#define HD_     64
#define ST_     128
#define NC_     8
#define CS_     256
#define MT      (Bb*Ll)      // 4096
#define NP1     8576         // PROJ_ padded to 67*128

#define RES_SCALE 2048.f
#define RES_INV   (1.f/2048.f)

// ---------------- static scratch (no allocations allowed) ----------------
__device__ float g_proj  [(size_t)MT*PROJ_];
__device__ float g_xbc   [(size_t)MT*CONVD_];
__device__ float g_y     [(size_t)MT*INTER_];
__device__ float g_states[(size_t)Bb*NC_*NH_*HD_*ST_];
__device__ float g_prev  [(size_t)Bb*NC_*NH_*HD_*ST_];
__device__ float g_cum   [(size_t)Bb*NH_*Ll];
__device__ float g_alast [(size_t)Bb*NH_*NC_];
__device__ float g_P     [(size_t)Bb*NC_*CS_*CS_];
__device__ __half g_Af [(size_t)MT*INTER_];
__device__ __half g_W1h[(size_t)NP1*HIDDEN_];
__device__ __half g_W1l[(size_t)NP1*HIDDEN_];
__device__ __half g_W2h[(size_t)HIDDEN_*INTER_];
__device__ __half g_W2l[(size_t)HIDDEN_*INTER_];

// ======================= warp-MMA helpers (sm_80 path) ====================
__device__ __forceinline__ uint32_t cvta_smem(const void* p) {
    uint32_t a;
    asm("{ .reg .u64 t; cvta.to.shared.u64 t, %1; cvt.u32.u64 %0, t; }"
        : "=r"(a) : "l"(p));
    return a;
}

__device__ __forceinline__ void ldsm4(uint32_t* r, uint32_t addr) {
    asm volatile("ldmatrix.sync.aligned.m8n8.x4.shared.b16 {%0,%1,%2,%3}, [%4];"
                 : "=r"(r[0]), "=r"(r[1]), "=r"(r[2]), "=r"(r[3]) : "r"(addr));
}

__device__ __forceinline__ void mma16816(float* c, const uint32_t* a,
                                         uint32_t b0, uint32_t b1) {
    asm volatile(
        "mma.sync.aligned.m16n8k16.row.col.f32.f16.f16.f32 "
        "{%0,%1,%2,%3}, {%4,%5,%6,%7}, {%8,%9}, {%0,%1,%2,%3};"
        : "+f"(c[0]), "+f"(c[1]), "+f"(c[2]), "+f"(c[3])
        : "r"(a[0]), "r"(a[1]), "r"(a[2]), "r"(a[3]), "r"(b0), "r"(b1));
}

__device__ __forceinline__ void mma16816h(uint32_t* c, const uint32_t* a,
                                          uint32_t b0, uint32_t b1) {
    asm volatile(
        "mma.sync.aligned.m16n8k16.row.col.f16.f16.f16.f16 "
        "{%0,%1}, {%2,%3,%4,%5}, {%6,%7}, {%0,%1};"
        : "+r"(c[0]), "+r"(c[1])
        : "r"(a[0]), "r"(a[1]), "r"(a[2]), "r"(a[3]), "r"(b0), "r"(b1));
}

#define CPASYNC16(sa, ga) \
    asm volatile("cp.async.cg.shared.global [%0], [%1], 16;" :: "r"(sa), "l"(ga) : "memory")

#define TILEB  16384u
#define STAGEB 49152u
#define NSTG   4
#define GSMEM  (1024 + NSTG*49152)   // 197632

// =========================================================================
// 2-pass fp16 tensor-core GEMM: C = A*(Wh + Wl/2048)^T + bias
// 16 warps (512 thr): warp (wm, wn) in 4x4 grid owns 32(M) x 32(N).
// =========================================================================
__global__ __launch_bounds__(512, 1)
void tc_gemm_bias(
    const __half* __restrict__ A,
    const __half* __restrict__ Wh, const __half* __restrict__ Wl,
    const float* __restrict__ bias, float* __restrict__ C, int N, int K)
{
    extern __shared__ __align__(128) char smem[];
    const int tid = threadIdx.x;
    const int lid = tid & 31, wid = tid >> 5;
    uint32_t sb = cvta_smem(smem);
    uint32_t tb = (sb + 1023u) & ~1023u;

    const size_t arow = (size_t)blockIdx.y * 128;
    const size_t brow = (size_t)blockIdx.x * 128;
    const int NCH = K >> 6;

    // ---- hoisted load addressing ----
    const int seg = tid & 7, r0 = tid >> 3;        // r0: 0..63
    uint32_t offA = (uint32_t)(r0 * 128 + seg * 16);
    uint32_t so0 = offA ^ ((offA >> 3) & 0x70);
    uint32_t offB = (uint32_t)((r0 + 64) * 128 + seg * 16);
    uint32_t so1 = offB ^ ((offB >> 3) & 0x70);
    const __half* pA  = A  + (arow + r0) * (size_t)K + (seg << 3);
    const __half* pWh = Wh + (brow + r0) * (size_t)K + (seg << 3);
    const __half* pWl = Wl + (brow + r0) * (size_t)K + (seg << 3);
    const size_t off64 = (size_t)64 * K;

#define LOAD_STAGE(s)                                                     \
    do {                                                                  \
        uint32_t stb_ = tb + (uint32_t)(s) * STAGEB;                      \
        CPASYNC16(stb_ + so0,             pA);                            \
        CPASYNC16(stb_ + so1,             pA + off64);                    \
        CPASYNC16(stb_ + TILEB + so0,     pWh);                           \
        CPASYNC16(stb_ + TILEB + so1,     pWh + off64);                   \
        CPASYNC16(stb_ + 2*TILEB + so0,   pWl);                           \
        CPASYNC16(stb_ + 2*TILEB + so1,   pWl + off64);                   \
        asm volatile("cp.async.commit_group;" ::: "memory");              \
        pA += 64; pWh += 64; pWl += 64;                                   \
    } while (0)

    const int wm = wid & 3, wn = wid >> 2;
    const int m0 = wm * 32, n0 = wn * 32;
    const int lr  = lid & 15;
    const int lkb = (lid >> 4) * 16;

    float acc1[2][4][4];
    uint32_t acc2[2][4][2];
#pragma unroll
    for (int mi = 0; mi < 2; mi++)
#pragma unroll
        for (int nj = 0; nj < 4; nj++) {
#pragma unroll
            for (int q = 0; q < 4; q++) acc1[mi][nj][q] = 0.f;
            acc2[mi][nj][0] = 0u; acc2[mi][nj][1] = 0u;
        }

    uint32_t aoff[2], boff[2];
#pragma unroll
    for (int mi = 0; mi < 2; mi++) {
        int row = m0 + mi * 16 + lr;
        aoff[mi] = (uint32_t)(row * 128) + (uint32_t)(((row & 7) * 16) ^ lkb);
    }
#pragma unroll
    for (int ni = 0; ni < 2; ni++) {
        int row = n0 + ni * 16 + lr;
        boff[ni] = (uint32_t)(row * 128) + (uint32_t)(((row & 7) * 16) ^ lkb);
    }

    LOAD_STAGE(0);
    LOAD_STAGE(1);
    LOAD_STAGE(2);

    for (int c = 0; c < NCH; c++) {
        if (c + 1 < NCH) asm volatile("cp.async.wait_group 2;" ::: "memory");
        else             asm volatile("cp.async.wait_group 0;" ::: "memory");
        __syncthreads();
        if (c + 3 < NCH) LOAD_STAGE((c + 3) & (NSTG - 1));

        uint32_t stb = tb + (uint32_t)(c & (NSTG - 1)) * STAGEB;
#pragma unroll
        for (int kk = 0; kk < 4; kk++) {
            uint32_t kx = (uint32_t)(kk * 32);
            uint32_t a_f[2][4];
#pragma unroll
            for (int mi = 0; mi < 2; mi++)
                ldsm4(a_f[mi], stb + (aoff[mi] ^ kx));
            uint32_t w_h[2][4], w_l[2][4];
#pragma unroll
            for (int ni = 0; ni < 2; ni++) {
                uint32_t bd = stb + (boff[ni] ^ kx);
                ldsm4(w_h[ni], bd + TILEB);
                ldsm4(w_l[ni], bd + 2*TILEB);
            }
#pragma unroll
            for (int mi = 0; mi < 2; mi++)
#pragma unroll
                for (int ni = 0; ni < 2; ni++) {
                    mma16816(acc1[mi][2*ni],    a_f[mi], w_h[ni][0], w_h[ni][2]);
                    mma16816h(acc2[mi][2*ni],   a_f[mi], w_l[ni][0], w_l[ni][2]);
                    mma16816(acc1[mi][2*ni+1],  a_f[mi], w_h[ni][1], w_h[ni][3]);
                    mma16816h(acc2[mi][2*ni+1], a_f[mi], w_l[ni][1], w_l[ni][3]);
                }
        }
        __syncthreads();
    }

    const int er = lid >> 2;
    const int ec = (lid & 3) * 2;
#pragma unroll
    for (int mi = 0; mi < 2; mi++) {
        int grow0 = (int)arow + m0 + mi * 16 + er;
#pragma unroll
        for (int nj = 0; nj < 4; nj++) {
            int gcol = (int)brow + n0 + nj * 8 + ec;
            float2 l0 = __half22float2(*(const __half2*)&acc2[mi][nj][0]);
            float2 l1 = __half22float2(*(const __half2*)&acc2[mi][nj][1]);
            if (gcol + 1 < N) {
                float b0 = __ldg(&bias[gcol]), b1 = __ldg(&bias[gcol + 1]);
                float2 v0 = {acc1[mi][nj][0] + l0.x * RES_INV + b0,
                             acc1[mi][nj][1] + l0.y * RES_INV + b1};
                float2 v1 = {acc1[mi][nj][2] + l1.x * RES_INV + b0,
                             acc1[mi][nj][3] + l1.y * RES_INV + b1};
                *(float2*)&C[(size_t)grow0 * N + gcol] = v0;
                *(float2*)&C[(size_t)(grow0 + 8) * N + gcol] = v1;
            } else if (gcol < N) {
                float b0 = __ldg(&bias[gcol]);
                C[(size_t)grow0 * N + gcol] = acc1[mi][nj][0] + l0.x * RES_INV + b0;
                C[(size_t)(grow0 + 8) * N + gcol] = acc1[mi][nj][2] + l1.x * RES_INV + b0;
            }
        }
    }
#undef LOAD_STAGE
}

// ---------------- fp32 -> fp16 conversions ---------------------------------
__global__ void cvt_fp16_kernel(const float4* __restrict__ src,
                                __half2* __restrict__ dst, size_t n4)
{
    size_t i = (size_t)blockIdx.x * blockDim.x + threadIdx.x;
    if (i >= n4) return;
    float4 v = src[i];
    dst[2*i]   = __floats2half2_rn(v.x, v.y);
    dst[2*i+1] = __floats2half2_rn(v.z, v.w);
}

__global__ void cvt_split_fp16_kernel(const float4* __restrict__ src,
                                      __half2* __restrict__ hi,
                                      __half2* __restrict__ lo,
                                      size_t n4v, size_t n4t)
{
    size_t i = (size_t)blockIdx.x * blockDim.x + threadIdx.x;
    if (i >= n4t) return;
    float4 v = (i < n4v) ? src[i] : make_float4(0.f, 0.f, 0.f, 0.f);
    __half h0 = __float2half_rn(v.x), h1 = __float2half_rn(v.y);
    __half h2 = __float2half_rn(v.z), h3 = __float2half_rn(v.w);
    hi[2*i]   = __halves2half2(h0, h1);
    hi[2*i+1] = __halves2half2(h2, h3);
    lo[2*i]   = __floats2half2_rn((v.x - __half2float(h0)) * RES_SCALE,
                                  (v.y - __half2float(h1)) * RES_SCALE);
    lo[2*i+1] = __floats2half2_rn((v.z - __half2float(h2)) * RES_SCALE,
                                  (v.w - __half2float(h3)) * RES_SCALE);
}

// ---------------- causal depthwise conv (K=4) + SiLU ----------------------
__global__ void conv_silu_kernel(const float* __restrict__ proj,
                                 const float* __restrict__ cw,
                                 float* __restrict__ xbc)
{
    int idx = blockIdx.x * 256 + threadIdx.x;
    if (idx >= Bb * Ll * CONVD_) return;
    int cidx = idx % CONVD_;
    int t = (idx / CONVD_) % Ll;
    int b = idx / (CONVD_ * Ll);
    const float* base = proj + (size_t)(b * Ll) * PROJ_ + INTER_ + cidx;
    float acc = 0.f;
#pragma unroll
    for (int j = 0; j < 4; j++) {
        int tt = t + j - 3;
        if (tt >= 0) acc = fmaf(base[(size_t)tt * PROJ_], cw[cidx * 4 + j], acc);
    }
    float sg = 1.f / (1.f + expf(-acc));
    xbc[idx] = acc * sg;
}

// ---------------- P = C * B^T, shared across heads -------------------------
__device__ __constant__ int c_PI[10] = {0,1,1,2,2,2,3,3,3,3};
__device__ __constant__ int c_PJ[10] = {0,0,1,0,1,2,0,1,2,3};

__global__ __launch_bounds__(256, 2) void pmat_kernel(
    const float* __restrict__ xbc, float* __restrict__ P)
{
    const int p = blockIdx.x, c = blockIdx.y, b = blockIdx.z;
    const int i = c_PI[p], j = c_PJ[p];
    const int tid = threadIdx.x;
    extern __shared__ float sm[];
    float* CsT = sm;              // [128][68]
    float* BsT = CsT + 128 * 68;  // [128][68]
    const size_t rowbase = (size_t)(b * Ll + c * CS_);

    for (int idx = tid; idx < 64 * 128; idx += 256) {
        int tl = idx >> 7, n = idx & 127;
        CsT[n * 68 + tl] = xbc[(rowbase + i * 64 + tl) * CONVD_ + (INTER_ + ST_) + n];
        BsT[n * 68 + tl] = xbc[(rowbase + j * 64 + tl) * CONVD_ + INTER_ + n];
    }
    __syncthreads();

    const int tx = tid & 15, ty = tid >> 4;
    const int t0 = ty * 4, s0 = tx * 4;
    float pf[4][4];
#pragma unroll
    for (int r = 0; r < 4; r++)
#pragma unroll
        for (int q = 0; q < 4; q++) pf[r][q] = 0.f;
    for (int n = 0; n < 128; n++) {
        float4 c4 = *(const float4*)&CsT[n * 68 + t0];
        float4 b4 = *(const float4*)&BsT[n * 68 + s0];
        float cr[4] = {c4.x, c4.y, c4.z, c4.w};
        float br[4] = {b4.x, b4.y, b4.z, b4.w};
#pragma unroll
        for (int r = 0; r < 4; r++)
#pragma unroll
            for (int q = 0; q < 4; q++)
                pf[r][q] = fmaf(cr[r], br[q], pf[r][q]);
    }
    float* dst = P + ((size_t)(b * NC_ + c) * CS_) * CS_;
#pragma unroll
    for (int r = 0; r < 4; r++) {
        float4 o = {pf[r][0], pf[r][1], pf[r][2], pf[r][3]};
        *(float4*)&dst[(size_t)(i * 64 + t0 + r) * CS_ + j * 64 + s0] = o;
    }
}

// ---------------- intra-chunk scan: Y_diag + per-chunk states -------------
// PsT stored transposed [s][t], B stored s-major [s][n] -> vectorized reads
__global__ __launch_bounds__(256, 2) void scan_intra_kernel(
    const float* __restrict__ proj, const float* __restrict__ xbc,
    const float* __restrict__ gP,
    const float* __restrict__ dt_bias, const float* __restrict__ A_log,
    float* __restrict__ ydiag, float* __restrict__ states,
    float* __restrict__ cumg, float* __restrict__ alast)
{
    const int h = blockIdx.x, c = blockIdx.y, b = blockIdx.z;
    const int tid = threadIdx.x;
    extern __shared__ float sm[];
    float* PsT   = sm;                // [64][68]  (s, t)
    float* xsm   = PsT + 64 * 68;     // [64][68]  (s, p)
    float* Bs    = xsm + 64 * 68;     // [64][132] (s, n)
    float* dsh   = Bs + 64 * 132;     // [256]
    float* cum   = dsh + 256;         // [256]
    float* wlast = cum + 256;         // [256]
    float* Esh   = wlast + 256;       // [64]
    float* Rsh   = Esh + 64;          // [64]

    {
        float Ah = -expf(A_log[h]);
        float v = proj[(size_t)(b * Ll + c * CS_ + tid) * PROJ_ + (INTER_ + CONVD_) + h]
                + dt_bias[h];
        float dtv = (v > 20.f) ? v : log1pf(expf(v));
        dsh[tid] = dtv;
        cum[tid] = Ah * dtv;
    }
    __syncthreads();
    for (int off = 1; off < 256; off <<= 1) {
        float add = (tid >= off) ? cum[tid - off] : 0.f;
        __syncthreads();
        cum[tid] += add;
        __syncthreads();
    }
    cumg[(size_t)(b * NH_ + h) * Ll + c * CS_ + tid] = cum[tid];
    if (tid == 255) alast[(b * NH_ + h) * NC_ + c] = cum[255];
    wlast[tid] = expf(cum[255] - cum[tid]);
    __syncthreads();

    const int tx = tid & 15, ty = tid >> 4;
    const int t0 = ty * 4, p0 = tx * 4;
    float stacc[4][8];
#pragma unroll
    for (int r = 0; r < 4; r++)
#pragma unroll
        for (int q = 0; q < 8; q++) stacc[r][q] = 0.f;

    const size_t rowbase = (size_t)(b * Ll + c * CS_);
    const float* Pblk = gP + ((size_t)(b * NC_ + c) * CS_) * CS_;

    for (int i = 0; i < 4; i++) {
        if (tid < 64) Esh[tid] = expf(cum[i * 64 + tid] - cum[i * 64]);
        float yacc[4][4];
#pragma unroll
        for (int r = 0; r < 4; r++)
#pragma unroll
            for (int q = 0; q < 4; q++) yacc[r][q] = 0.f;

        for (int j = 0; j <= i; j++) {
            __syncthreads();
            for (int idx = tid; idx < 64 * 64; idx += 256) {
                int sl = idx >> 6, p = idx & 63;
                xsm[sl * 68 + p] =
                    xbc[(rowbase + j * 64 + sl) * CONVD_ + h * HD_ + p]
                    * dsh[j * 64 + sl];
            }
            if (j < i && tid < 64)
                Rsh[tid] = expf(cum[i * 64] - cum[j * 64 + tid]);
            if (j == i) {
                for (int idx = tid; idx < 64 * 128; idx += 256) {
                    int sl = idx >> 7, n = idx & 127;
                    Bs[sl * 132 + n] =
                        xbc[(rowbase + j * 64 + sl) * CONVD_ + INTER_ + n];
                }
            }
            __syncthreads();

            if (j == i) {
                int n0 = ty * 8;
                for (int sl = 0; sl < 64; sl++) {
                    float w = wlast[i * 64 + sl];
                    float4 x4 = *(const float4*)&xsm[sl * 68 + p0];
                    float xv[4] = {x4.x * w, x4.y * w, x4.z * w, x4.w * w};
                    float4 b0 = *(const float4*)&Bs[sl * 132 + n0];
                    float4 b1 = *(const float4*)&Bs[sl * 132 + n0 + 4];
                    float bv[8] = {b0.x, b0.y, b0.z, b0.w, b1.x, b1.y, b1.z, b1.w};
#pragma unroll
                    for (int q = 0; q < 8; q++)
#pragma unroll
                        for (int r = 0; r < 4; r++)
                            stacc[r][q] = fmaf(xv[r], bv[q], stacc[r][q]);
                }
                // diagonal tile: elementwise exp with causal mask (transposed)
                for (int idx = tid; idx < 64 * 64; idx += 256) {
                    int tl = idx >> 6, s = idx & 63;
                    float w = (s <= tl) ? expf(cum[i*64 + tl] - cum[i*64 + s]) : 0.f;
                    PsT[s * 68 + tl] = Pblk[(size_t)(i*64 + tl) * CS_ + i*64 + s] * w;
                }
            } else {
                for (int idx = tid; idx < 64 * 64; idx += 256) {
                    int tl = idx >> 6, s = idx & 63;
                    PsT[s * 68 + tl] = Pblk[(size_t)(i*64 + tl) * CS_ + j*64 + s]
                                       * Esh[tl] * Rsh[s];
                }
            }
            __syncthreads();
            // Y_i += PsT^T @ (x*dt)   (both reads vectorized)
            for (int sl = 0; sl < 64; sl++) {
                float4 x4 = *(const float4*)&xsm[sl * 68 + p0];
                float4 pw = *(const float4*)&PsT[sl * 68 + t0];
                float pr[4] = {pw.x, pw.y, pw.z, pw.w};
#pragma unroll
                for (int r = 0; r < 4; r++) {
                    yacc[r][0] = fmaf(pr[r], x4.x, yacc[r][0]);
                    yacc[r][1] = fmaf(pr[r], x4.y, yacc[r][1]);
                    yacc[r][2] = fmaf(pr[r], x4.z, yacc[r][2]);
                    yacc[r][3] = fmaf(pr[r], x4.w, yacc[r][3]);
                }
            }
        }
        {
#pragma unroll
            for (int r = 0; r < 4; r++) {
                size_t tg = rowbase + i * 64 + t0 + r;
                float4 o = {yacc[r][0], yacc[r][1], yacc[r][2], yacc[r][3]};
                *(float4*)&ydiag[(tg * NH_ + h) * HD_ + p0] = o;
            }
        }
    }
    {
        int n0 = ty * 8;
        size_t base = ((size_t)((b * NC_ + c) * NH_ + h)) * HD_;
#pragma unroll
        for (int r = 0; r < 4; r++) {
            float4 o0 = {stacc[r][0], stacc[r][1], stacc[r][2], stacc[r][3]};
            float4 o1 = {stacc[r][4], stacc[r][5], stacc[r][6], stacc[r][7]};
            float* dst = states + (base + p0 + r) * ST_ + n0;
            *(float4*)dst = o0;
            *(float4*)(dst + 4) = o1;
        }
    }
}

// ---------------- inter-chunk recurrence -----------------------------------
__global__ void interchunk_kernel(const float* __restrict__ states,
                                  const float* __restrict__ alast,
                                  float* __restrict__ prev)
{
    int bh = blockIdx.x;
    int b = bh >> 6, h = bh & 63;
    float dec[NC_];
#pragma unroll
    for (int c = 0; c < NC_; c++)
        dec[c] = expf(alast[(b * NH_ + h) * NC_ + c]);
    for (int e = threadIdx.x; e < HD_ * ST_; e += 256) {
        float run = 0.f;
#pragma unroll
        for (int c = 0; c < NC_; c++) {
            size_t idx = ((size_t)((b * NC_ + c) * NH_ + h)) * (HD_ * ST_) + e;
            prev[idx] = run;
            run = fmaf(run, dec[c] - 1.f, run);
            run = run + states[idx];
        }
    }
}

// ---------------- Y_off + D-skip, accumulate into y ------------------------
__global__ __launch_bounds__(256, 2) void scan_off_kernel(
    const float* __restrict__ xbc, const float* __restrict__ cumg,
    const float* __restrict__ prev, const float* __restrict__ Dv,
    float* __restrict__ y)
{
    const int h = blockIdx.x, c = blockIdx.y, b = blockIdx.z;
    const int tid = threadIdx.x;
    extern __shared__ float sm[];
    float* pvsT = sm;                  // [128][68]  (n, p)
    float* CsT  = pvsT + 128 * 68;     // [128][68]  (n, t)
    float* esh  = CsT + 128 * 68;      // [256]
    size_t sbase = ((size_t)((b * NC_ + c) * NH_ + h)) * (HD_ * ST_);
    for (int idx = tid; idx < 64 * 128; idx += 256) {
        int p = idx >> 7, n = idx & 127;
        pvsT[n * 68 + p] = prev[sbase + idx];
    }
    esh[tid] = expf(cumg[(size_t)(b * NH_ + h) * Ll + c * CS_ + tid]);
    const float Dh = Dv[h];
    const int tx = tid & 15, ty = tid >> 4;
    const size_t rowbase = (size_t)(b * Ll + c * CS_);
    for (int ti = 0; ti < 4; ti++) {
        __syncthreads();
        for (int idx = tid; idx < 64 * 128; idx += 256) {
            int tl = idx >> 7, n = idx & 127;
            CsT[n * 68 + tl] =
                xbc[(rowbase + ti * 64 + tl) * CONVD_ + (INTER_ + ST_) + n];
        }
        __syncthreads();
        int t0 = ty * 4, p0 = tx * 4;
        float acc[4][4];
#pragma unroll
        for (int r = 0; r < 4; r++)
#pragma unroll
            for (int q = 0; q < 4; q++) acc[r][q] = 0.f;
        for (int n = 0; n < 128; n++) {
            float4 c4 = *(const float4*)&CsT[n * 68 + t0];
            float4 p4 = *(const float4*)&pvsT[n * 68 + p0];
            float cr[4] = {c4.x, c4.y, c4.z, c4.w};
            float pv[4] = {p4.x, p4.y, p4.z, p4.w};
#pragma unroll
            for (int r = 0; r < 4; r++)
#pragma unroll
                for (int q = 0; q < 4; q++)
                    acc[r][q] = fmaf(cr[r], pv[q], acc[r][q]);
        }
#pragma unroll
        for (int r = 0; r < 4; r++) {
            size_t tg = rowbase + ti * 64 + t0 + r;
            float e = esh[ti * 64 + t0 + r];
            float* yp = y + (tg * NH_ + h) * HD_ + p0;
            float4 yv = *(float4*)yp;
            const float4 xv = *(const float4*)&xbc[tg * CONVD_ + h * HD_ + p0];
            yv.x += acc[r][0] * e + Dh * xv.x;
            yv.y += acc[r][1] * e + Dh * xv.y;
            yv.z += acc[r][2] * e + Dh * xv.z;
            yv.w += acc[r][3] * e + Dh * xv.w;
            *(float4*)yp = yv;
        }
    }
}

// ---------------- gated RMSNorm -> fp16 A for GEMM2 ------------------------
__global__ __launch_bounds__(256) void gated_norm_kernel(
    const float* __restrict__ proj, const float* __restrict__ y,
    const float* __restrict__ nw, __half* __restrict__ gf)
{
    int row = blockIdx.x;
    int tid = threadIdx.x;
    float gv[16];
    float ss = 0.f;
    const float* yr = y + (size_t)row * INTER_;
    const float* gr = proj + (size_t)row * PROJ_;
#pragma unroll
    for (int k = 0; k < 16; k++) {
        int idx = tid + k * 256;
        float gt = gr[idx];
        float s = 1.f / (1.f + expf(-gt));
        float v = yr[idx] * gt * s;
        gv[k] = v;
        ss = fmaf(v, v, ss);
    }
    __shared__ float red[256];
    red[tid] = ss;
    __syncthreads();
    for (int off = 128; off > 0; off >>= 1) {
        if (tid < off) red[tid] += red[tid + off];
        __syncthreads();
    }
    float scale = rsqrtf(red[0] / (float)INTER_ + 1e-5f);
#pragma unroll
    for (int k = 0; k < 16; k++) {
        int idx = tid + k * 256;
        gf[(size_t)row * INTER_ + idx] = __float2half_rn(gv[k] * scale * nw[idx]);
    }
}

// ---------------- launch ----------------------------------------------------
extern "C" void kernel_launch(void* const* d_in, const int* in_sizes, int n_in,
                              void* d_out, int out_size)
{
    const float* hidden  = (const float*)d_in[0];
    const float* in_w    = (const float*)d_in[1];
    const float* in_b    = (const float*)d_in[2];
    const float* conv_w  = (const float*)d_in[3];
    const float* dt_bias = (const float*)d_in[4];
    const float* A_log   = (const float*)d_in[5];
    const float* Dv      = (const float*)d_in[6];
    const float* norm_w  = (const float*)d_in[7];
    const float* out_w   = (const float*)d_in[8];
    const float* out_b   = (const float*)d_in[9];
    float* out = (float*)d_out;

    float *proj, *xbc, *y, *states, *prev, *cum, *al, *Pm;
    __half *Af, *W1h, *W1l, *W2h, *W2l;
    cudaGetSymbolAddress((void**)&proj,   g_proj);
    cudaGetSymbolAddress((void**)&xbc,    g_xbc);
    cudaGetSymbolAddress((void**)&y,      g_y);
    cudaGetSymbolAddress((void**)&states, g_states);
    cudaGetSymbolAddress((void**)&prev,   g_prev);
    cudaGetSymbolAddress((void**)&cum,    g_cum);
    cudaGetSymbolAddress((void**)&al,     g_alast);
    cudaGetSymbolAddress((void**)&Pm,     g_P);
    cudaGetSymbolAddress((void**)&Af,     g_Af);
    cudaGetSymbolAddress((void**)&W1h,    g_W1h);
    cudaGetSymbolAddress((void**)&W1l,    g_W1l);
    cudaGetSymbolAddress((void**)&W2h,    g_W2h);
    cudaGetSymbolAddress((void**)&W2l,    g_W2l);

    const int SMEM_PMAT  = (128 * 68 * 2) * 4;
    const int SMEM_INTRA = (64*68*2 + 64*132 + 256*3 + 128) * 4;      //  73984
    const int SMEM_OFF   = (128*68*2 + 256) * 4;                      //  70656
    cudaFuncSetAttribute(pmat_kernel,
                         cudaFuncAttributeMaxDynamicSharedMemorySize, SMEM_PMAT);
    cudaFuncSetAttribute(scan_intra_kernel,
                         cudaFuncAttributeMaxDynamicSharedMemorySize, SMEM_INTRA);
    cudaFuncSetAttribute(scan_off_kernel,
                         cudaFuncAttributeMaxDynamicSharedMemorySize, SMEM_OFF);
    cudaFuncSetAttribute(tc_gemm_bias,
                         cudaFuncAttributeMaxDynamicSharedMemorySize, GSMEM);

    // 0. fp16 conversions
    {
        size_t n4 = (size_t)MT * HIDDEN_ / 4;
        cvt_fp16_kernel<<<(int)((n4 + 255) / 256), 256>>>(
            (const float4*)hidden, (__half2*)Af, n4);
        size_t n4v = (size_t)PROJ_ * HIDDEN_ / 4, n4t = (size_t)NP1 * HIDDEN_ / 4;
        cvt_split_fp16_kernel<<<(int)((n4t + 255) / 256), 256>>>(
            (const float4*)in_w, (__half2*)W1h, (__half2*)W1l, n4v, n4t);
        n4 = (size_t)HIDDEN_ * INTER_ / 4;
        cvt_split_fp16_kernel<<<(int)((n4 + 255) / 256), 256>>>(
            (const float4*)out_w, (__half2*)W2h, (__half2*)W2l, n4, n4);
    }

    // 1. in_proj GEMM + bias (2-pass fp16 mma.sync)
    tc_gemm_bias<<<dim3(NP1 / 128, MT / 128), 512, GSMEM>>>(
        Af, W1h, W1l, in_b, proj, PROJ_, HIDDEN_);

    // 2. causal depthwise conv + SiLU
    conv_silu_kernel<<<(Bb * Ll * CONVD_ + 255) / 256, 256>>>(proj, conv_w, xbc);

    // 2b. shared P = C * B^T per (b, chunk)
    pmat_kernel<<<dim3(10, NC_, Bb), 256, SMEM_PMAT>>>(xbc, Pm);

    // 3. intra-chunk scan (per head, reusing P)
    scan_intra_kernel<<<dim3(NH_, NC_, Bb), 256, SMEM_INTRA>>>(
        proj, xbc, Pm, dt_bias, A_log, y, states, cum, al);

    // 4. inter-chunk recurrence
    interchunk_kernel<<<Bb * NH_, 256>>>(states, al, prev);

    // 5. inter-chunk output contribution + D skip
    scan_off_kernel<<<dim3(NH_, NC_, Bb), 256, SMEM_OFF>>>(xbc, cum, prev, Dv, y);

    // 6. gated RMSNorm -> fp16 A for GEMM2 (reuses Af)
    gated_norm_kernel<<<MT, 256>>>(proj, y, norm_w, Af);

    // 7. out_proj GEMM + bias (2-pass fp16 mma.sync)
    tc_gemm_bias<<<dim3(HIDDEN_ / 128, MT / 128), 512, GSMEM>>>(
        Af, W2h, W2l, out_b, out, HIDDEN_, INTER_);
}

// round 7
// speedup vs baseline: 3.7494x; 1.0884x over previous
#include <cuda_runtime.h>
#include <cuda_bf16.h>
#include <cuda_fp16.h>
#include <math.h>
#include <cstdint>

#define Bb      2
#define Ll      2048
#define HIDDEN_ 2048
#define PROJ_   8512
#define INTER_  4096
#define CONVD_  4352
#define NH_     64
#define HD_     64
#define ST_     128
#define NC_     8
#define CS_     256
#define MT      (Bb*Ll)      // 4096
#define NP1     8576         // PROJ_ padded to 134*64

#define RES_SCALE 2048.f
#define RES_INV   (1.f/2048.f)

// ---------------- static scratch (no allocations allowed) ----------------
__device__ float g_proj  [(size_t)MT*PROJ_];
__device__ float g_xbc   [(size_t)MT*CONVD_];
__device__ float g_y     [(size_t)MT*INTER_];
__device__ float g_states[(size_t)Bb*NC_*NH_*HD_*ST_];
__device__ float g_prev  [(size_t)Bb*NC_*NH_*HD_*ST_];
__device__ float g_cum   [(size_t)Bb*NH_*Ll];
__device__ float g_alast [(size_t)Bb*NH_*NC_];
__device__ float g_P     [(size_t)Bb*NC_*CS_*CS_];
__device__ __half g_Af [(size_t)MT*INTER_];
__device__ __half g_W1h[(size_t)NP1*HIDDEN_];
__device__ __half g_W1l[(size_t)NP1*HIDDEN_];
__device__ __half g_W2h[(size_t)HIDDEN_*INTER_];
__device__ __half g_W2l[(size_t)HIDDEN_*INTER_];

// ======================= warp-MMA helpers (sm_80 path) ====================
__device__ __forceinline__ uint32_t cvta_smem(const void* p) {
    uint32_t a;
    asm("{ .reg .u64 t; cvta.to.shared.u64 t, %1; cvt.u32.u64 %0, t; }"
        : "=r"(a) : "l"(p));
    return a;
}

__device__ __forceinline__ void ldsm4(uint32_t* r, uint32_t addr) {
    asm volatile("ldmatrix.sync.aligned.m8n8.x4.shared.b16 {%0,%1,%2,%3}, [%4];"
                 : "=r"(r[0]), "=r"(r[1]), "=r"(r[2]), "=r"(r[3]) : "r"(addr));
}

__device__ __forceinline__ void mma16816(float* c, const uint32_t* a,
                                         uint32_t b0, uint32_t b1) {
    asm volatile(
        "mma.sync.aligned.m16n8k16.row.col.f32.f16.f16.f32 "
        "{%0,%1,%2,%3}, {%4,%5,%6,%7}, {%8,%9}, {%0,%1,%2,%3};"
        : "+f"(c[0]), "+f"(c[1]), "+f"(c[2]), "+f"(c[3])
        : "r"(a[0]), "r"(a[1]), "r"(a[2]), "r"(a[3]), "r"(b0), "r"(b1));
}

__device__ __forceinline__ void mma16816h(uint32_t* c, const uint32_t* a,
                                          uint32_t b0, uint32_t b1) {
    asm volatile(
        "mma.sync.aligned.m16n8k16.row.col.f16.f16.f16.f16 "
        "{%0,%1}, {%2,%3,%4,%5}, {%6,%7}, {%0,%1};"
        : "+r"(c[0]), "+r"(c[1])
        : "r"(a[0]), "r"(a[1]), "r"(a[2]), "r"(a[3]), "r"(b0), "r"(b1));
}

#define CPASYNC16(sa, ga) \
    asm volatile("cp.async.cg.shared.global [%0], [%1], 16;" :: "r"(sa), "l"(ga) : "memory")

// GEMM tiling: BM=128, BN=64, BK=64, 256 threads, 2 CTAs/SM, 3 stages
#define ATILEB 16384u
#define WTILEB 8192u
#define STAGEB 32768u
#define NSTG   3
#define GSMEM  (1024 + NSTG*32768)   // 99328

// =========================================================================
// 2-pass fp16 tensor-core GEMM: C = A*(Wh + Wl/2048)^T + bias
// 8 warps: warp (wm 0..3, wn 0..1) owns 32(M) x 32(N).
// =========================================================================
__global__ __launch_bounds__(256, 2)
void tc_gemm_bias(
    const __half* __restrict__ A,
    const __half* __restrict__ Wh, const __half* __restrict__ Wl,
    const float* __restrict__ bias, float* __restrict__ C, int N, int K)
{
    extern __shared__ __align__(128) char smem[];
    const int tid = threadIdx.x;
    const int lid = tid & 31, wid = tid >> 5;
    uint32_t sb = cvta_smem(smem);
    uint32_t tb = (sb + 1023u) & ~1023u;

    const size_t arow = (size_t)blockIdx.y * 128;
    const size_t brow = (size_t)blockIdx.x * 64;
    const int NCH = K >> 6;

    // ---- hoisted load addressing: 256 threads fill 32KB/stage ----
    const int seg = tid & 7, r0 = tid >> 3;       // r0: 0..31
    uint32_t soA[4], soW[2];
#pragma unroll
    for (int k = 0; k < 4; k++) {
        uint32_t off = (uint32_t)((r0 + 32 * k) * 128 + seg * 16);
        soA[k] = off ^ ((off >> 3) & 0x70);
    }
#pragma unroll
    for (int k = 0; k < 2; k++) {
        uint32_t off = (uint32_t)((r0 + 32 * k) * 128 + seg * 16);
        soW[k] = off ^ ((off >> 3) & 0x70);
    }
    const __half* pA  = A  + (arow + r0) * (size_t)K + (seg << 3);
    const __half* pWh = Wh + (brow + r0) * (size_t)K + (seg << 3);
    const __half* pWl = Wl + (brow + r0) * (size_t)K + (seg << 3);
    const size_t off32 = (size_t)32 * K;

#define LOAD_STAGE(s)                                                     \
    do {                                                                  \
        uint32_t stb_ = tb + (uint32_t)(s) * STAGEB;                      \
        CPASYNC16(stb_ + soA[0], pA);                                     \
        CPASYNC16(stb_ + soA[1], pA + off32);                             \
        CPASYNC16(stb_ + soA[2], pA + 2 * off32);                         \
        CPASYNC16(stb_ + soA[3], pA + 3 * off32);                         \
        CPASYNC16(stb_ + ATILEB + soW[0],          pWh);                  \
        CPASYNC16(stb_ + ATILEB + soW[1],          pWh + off32);          \
        CPASYNC16(stb_ + ATILEB + WTILEB + soW[0], pWl);                  \
        CPASYNC16(stb_ + ATILEB + WTILEB + soW[1], pWl + off32);          \
        asm volatile("cp.async.commit_group;" ::: "memory");              \
        pA += 64; pWh += 64; pWl += 64;                                   \
    } while (0)

    const int wm = wid & 3, wn = wid >> 2;        // 4 x 2 warp grid
    const int m0 = wm * 32, n0 = wn * 32;
    const int lr  = lid & 15;
    const int lkb = (lid >> 4) * 16;

    float acc1[2][4][4];
    uint32_t acc2[2][4][2];
#pragma unroll
    for (int mi = 0; mi < 2; mi++)
#pragma unroll
        for (int nj = 0; nj < 4; nj++) {
#pragma unroll
            for (int q = 0; q < 4; q++) acc1[mi][nj][q] = 0.f;
            acc2[mi][nj][0] = 0u; acc2[mi][nj][1] = 0u;
        }

    uint32_t aoff[2], boff[2];
#pragma unroll
    for (int mi = 0; mi < 2; mi++) {
        int row = m0 + mi * 16 + lr;
        aoff[mi] = (uint32_t)(row * 128) + (uint32_t)(((row & 7) * 16) ^ lkb);
    }
#pragma unroll
    for (int ni = 0; ni < 2; ni++) {
        int row = n0 + ni * 16 + lr;
        boff[ni] = (uint32_t)(row * 128) + (uint32_t)(((row & 7) * 16) ^ lkb);
    }

    LOAD_STAGE(0);
    LOAD_STAGE(1);

    for (int c = 0; c < NCH; c++) {
        if (c + 1 < NCH) asm volatile("cp.async.wait_group 1;" ::: "memory");
        else             asm volatile("cp.async.wait_group 0;" ::: "memory");
        __syncthreads();   // single barrier per chunk: also fences stage reuse
        if (c + 2 < NCH) LOAD_STAGE((c + 2) % NSTG);

        uint32_t stb = tb + (uint32_t)(c % NSTG) * STAGEB;
#pragma unroll
        for (int kk = 0; kk < 4; kk++) {
            uint32_t kx = (uint32_t)(kk * 32);
            uint32_t a_f[2][4];
#pragma unroll
            for (int mi = 0; mi < 2; mi++)
                ldsm4(a_f[mi], stb + (aoff[mi] ^ kx));
            uint32_t w_h[2][4], w_l[2][4];
#pragma unroll
            for (int ni = 0; ni < 2; ni++) {
                uint32_t bd = stb + ATILEB + (boff[ni] ^ kx);
                ldsm4(w_h[ni], bd);
                ldsm4(w_l[ni], bd + WTILEB);
            }
#pragma unroll
            for (int mi = 0; mi < 2; mi++)
#pragma unroll
                for (int ni = 0; ni < 2; ni++) {
                    mma16816(acc1[mi][2*ni],    a_f[mi], w_h[ni][0], w_h[ni][2]);
                    mma16816h(acc2[mi][2*ni],   a_f[mi], w_l[ni][0], w_l[ni][2]);
                    mma16816(acc1[mi][2*ni+1],  a_f[mi], w_h[ni][1], w_h[ni][3]);
                    mma16816h(acc2[mi][2*ni+1], a_f[mi], w_l[ni][1], w_l[ni][3]);
                }
        }
    }

    const int er = lid >> 2;
    const int ec = (lid & 3) * 2;
#pragma unroll
    for (int mi = 0; mi < 2; mi++) {
        int grow0 = (int)arow + m0 + mi * 16 + er;
#pragma unroll
        for (int nj = 0; nj < 4; nj++) {
            int gcol = (int)brow + n0 + nj * 8 + ec;
            float2 l0 = __half22float2(*(const __half2*)&acc2[mi][nj][0]);
            float2 l1 = __half22float2(*(const __half2*)&acc2[mi][nj][1]);
            if (gcol + 1 < N) {
                float b0 = __ldg(&bias[gcol]), b1 = __ldg(&bias[gcol + 1]);
                float2 v0 = {acc1[mi][nj][0] + l0.x * RES_INV + b0,
                             acc1[mi][nj][1] + l0.y * RES_INV + b1};
                float2 v1 = {acc1[mi][nj][2] + l1.x * RES_INV + b0,
                             acc1[mi][nj][3] + l1.y * RES_INV + b1};
                *(float2*)&C[(size_t)grow0 * N + gcol] = v0;
                *(float2*)&C[(size_t)(grow0 + 8) * N + gcol] = v1;
            } else if (gcol < N) {
                float b0 = __ldg(&bias[gcol]);
                C[(size_t)grow0 * N + gcol] = acc1[mi][nj][0] + l0.x * RES_INV + b0;
                C[(size_t)(grow0 + 8) * N + gcol] = acc1[mi][nj][2] + l1.x * RES_INV + b0;
            }
        }
    }
#undef LOAD_STAGE
}

// ---------------- fp32 -> fp16 conversions ---------------------------------
__global__ void cvt_fp16_kernel(const float4* __restrict__ src,
                                __half2* __restrict__ dst, size_t n4)
{
    size_t i = (size_t)blockIdx.x * blockDim.x + threadIdx.x;
    if (i >= n4) return;
    float4 v = src[i];
    dst[2*i]   = __floats2half2_rn(v.x, v.y);
    dst[2*i+1] = __floats2half2_rn(v.z, v.w);
}

__global__ void cvt_split_fp16_kernel(const float4* __restrict__ src,
                                      __half2* __restrict__ hi,
                                      __half2* __restrict__ lo,
                                      size_t n4v, size_t n4t)
{
    size_t i = (size_t)blockIdx.x * blockDim.x + threadIdx.x;
    if (i >= n4t) return;
    float4 v = (i < n4v) ? src[i] : make_float4(0.f, 0.f, 0.f, 0.f);
    __half h0 = __float2half_rn(v.x), h1 = __float2half_rn(v.y);
    __half h2 = __float2half_rn(v.z), h3 = __float2half_rn(v.w);
    hi[2*i]   = __halves2half2(h0, h1);
    hi[2*i+1] = __halves2half2(h2, h3);
    lo[2*i]   = __floats2half2_rn((v.x - __half2float(h0)) * RES_SCALE,
                                  (v.y - __half2float(h1)) * RES_SCALE);
    lo[2*i+1] = __floats2half2_rn((v.z - __half2float(h2)) * RES_SCALE,
                                  (v.w - __half2float(h3)) * RES_SCALE);
}

// ---------------- causal depthwise conv (K=4) + SiLU ----------------------
__global__ void conv_silu_kernel(const float* __restrict__ proj,
                                 const float* __restrict__ cw,
                                 float* __restrict__ xbc)
{
    int idx = blockIdx.x * 256 + threadIdx.x;
    if (idx >= Bb * Ll * CONVD_) return;
    int cidx = idx % CONVD_;
    int t = (idx / CONVD_) % Ll;
    int b = idx / (CONVD_ * Ll);
    const float* base = proj + (size_t)(b * Ll) * PROJ_ + INTER_ + cidx;
    float acc = 0.f;
#pragma unroll
    for (int j = 0; j < 4; j++) {
        int tt = t + j - 3;
        if (tt >= 0) acc = fmaf(base[(size_t)tt * PROJ_], cw[cidx * 4 + j], acc);
    }
    float sg = 1.f / (1.f + expf(-acc));
    xbc[idx] = acc * sg;
}

// ---------------- P = C * B^T, shared across heads -------------------------
__device__ __constant__ int c_PI[10] = {0,1,1,2,2,2,3,3,3,3};
__device__ __constant__ int c_PJ[10] = {0,0,1,0,1,2,0,1,2,3};

__global__ __launch_bounds__(256, 2) void pmat_kernel(
    const float* __restrict__ xbc, float* __restrict__ P)
{
    const int p = blockIdx.x, c = blockIdx.y, b = blockIdx.z;
    const int i = c_PI[p], j = c_PJ[p];
    const int tid = threadIdx.x;
    extern __shared__ float sm[];
    float* CsT = sm;              // [128][68]
    float* BsT = CsT + 128 * 68;  // [128][68]
    const size_t rowbase = (size_t)(b * Ll + c * CS_);

    for (int idx = tid; idx < 64 * 128; idx += 256) {
        int tl = idx >> 7, n = idx & 127;
        CsT[n * 68 + tl] = xbc[(rowbase + i * 64 + tl) * CONVD_ + (INTER_ + ST_) + n];
        BsT[n * 68 + tl] = xbc[(rowbase + j * 64 + tl) * CONVD_ + INTER_ + n];
    }
    __syncthreads();

    const int tx = tid & 15, ty = tid >> 4;
    const int t0 = ty * 4, s0 = tx * 4;
    float pf[4][4];
#pragma unroll
    for (int r = 0; r < 4; r++)
#pragma unroll
        for (int q = 0; q < 4; q++) pf[r][q] = 0.f;
    for (int n = 0; n < 128; n++) {
        float4 c4 = *(const float4*)&CsT[n * 68 + t0];
        float4 b4 = *(const float4*)&BsT[n * 68 + s0];
        float cr[4] = {c4.x, c4.y, c4.z, c4.w};
        float br[4] = {b4.x, b4.y, b4.z, b4.w};
#pragma unroll
        for (int r = 0; r < 4; r++)
#pragma unroll
            for (int q = 0; q < 4; q++)
                pf[r][q] = fmaf(cr[r], br[q], pf[r][q]);
    }
    float* dst = P + ((size_t)(b * NC_ + c) * CS_) * CS_;
#pragma unroll
    for (int r = 0; r < 4; r++) {
        float4 o = {pf[r][0], pf[r][1], pf[r][2], pf[r][3]};
        *(float4*)&dst[(size_t)(i * 64 + t0 + r) * CS_ + j * 64 + s0] = o;
    }
}

// ---------------- intra-chunk scan: Y_diag + per-chunk states -------------
__global__ __launch_bounds__(256, 2) void scan_intra_kernel(
    const float* __restrict__ proj, const float* __restrict__ xbc,
    const float* __restrict__ gP,
    const float* __restrict__ dt_bias, const float* __restrict__ A_log,
    float* __restrict__ ydiag, float* __restrict__ states,
    float* __restrict__ cumg, float* __restrict__ alast)
{
    const int h = blockIdx.x, c = blockIdx.y, b = blockIdx.z;
    const int tid = threadIdx.x;
    extern __shared__ float sm[];
    float* PsT   = sm;                // [64][68]  (s, t)
    float* xsm   = PsT + 64 * 68;     // [64][68]  (s, p)
    float* Bs    = xsm + 64 * 68;     // [64][132] (s, n)
    float* dsh   = Bs + 64 * 132;     // [256]
    float* cum   = dsh + 256;         // [256]
    float* wlast = cum + 256;         // [256]
    float* Esh   = wlast + 256;       // [64]
    float* Rsh   = Esh + 64;          // [64]

    {
        float Ah = -expf(A_log[h]);
        float v = proj[(size_t)(b * Ll + c * CS_ + tid) * PROJ_ + (INTER_ + CONVD_) + h]
                + dt_bias[h];
        float dtv = (v > 20.f) ? v : log1pf(expf(v));
        dsh[tid] = dtv;
        cum[tid] = Ah * dtv;
    }
    __syncthreads();
    for (int off = 1; off < 256; off <<= 1) {
        float add = (tid >= off) ? cum[tid - off] : 0.f;
        __syncthreads();
        cum[tid] += add;
        __syncthreads();
    }
    cumg[(size_t)(b * NH_ + h) * Ll + c * CS_ + tid] = cum[tid];
    if (tid == 255) alast[(b * NH_ + h) * NC_ + c] = cum[255];
    wlast[tid] = expf(cum[255] - cum[tid]);
    __syncthreads();

    const int tx = tid & 15, ty = tid >> 4;
    const int t0 = ty * 4, p0 = tx * 4;
    float stacc[4][8];
#pragma unroll
    for (int r = 0; r < 4; r++)
#pragma unroll
        for (int q = 0; q < 8; q++) stacc[r][q] = 0.f;

    const size_t rowbase = (size_t)(b * Ll + c * CS_);
    const float* Pblk = gP + ((size_t)(b * NC_ + c) * CS_) * CS_;

    for (int i = 0; i < 4; i++) {
        if (tid < 64) Esh[tid] = expf(cum[i * 64 + tid] - cum[i * 64]);
        float yacc[4][4];
#pragma unroll
        for (int r = 0; r < 4; r++)
#pragma unroll
            for (int q = 0; q < 4; q++) yacc[r][q] = 0.f;

        for (int j = 0; j <= i; j++) {
            __syncthreads();
            for (int idx = tid; idx < 64 * 64; idx += 256) {
                int sl = idx >> 6, p = idx & 63;
                xsm[sl * 68 + p] =
                    xbc[(rowbase + j * 64 + sl) * CONVD_ + h * HD_ + p]
                    * dsh[j * 64 + sl];
            }
            if (j < i && tid < 64)
                Rsh[tid] = expf(cum[i * 64] - cum[j * 64 + tid]);
            if (j == i) {
                for (int idx = tid; idx < 64 * 128; idx += 256) {
                    int sl = idx >> 7, n = idx & 127;
                    Bs[sl * 132 + n] =
                        xbc[(rowbase + j * 64 + sl) * CONVD_ + INTER_ + n];
                }
            }
            __syncthreads();

            if (j == i) {
                int n0 = ty * 8;
                for (int sl = 0; sl < 64; sl++) {
                    float w = wlast[i * 64 + sl];
                    float4 x4 = *(const float4*)&xsm[sl * 68 + p0];
                    float xv[4] = {x4.x * w, x4.y * w, x4.z * w, x4.w * w};
                    float4 b0 = *(const float4*)&Bs[sl * 132 + n0];
                    float4 b1 = *(const float4*)&Bs[sl * 132 + n0 + 4];
                    float bv[8] = {b0.x, b0.y, b0.z, b0.w, b1.x, b1.y, b1.z, b1.w};
#pragma unroll
                    for (int q = 0; q < 8; q++)
#pragma unroll
                        for (int r = 0; r < 4; r++)
                            stacc[r][q] = fmaf(xv[r], bv[q], stacc[r][q]);
                }
                for (int idx = tid; idx < 64 * 64; idx += 256) {
                    int tl = idx >> 6, s = idx & 63;
                    float w = (s <= tl) ? expf(cum[i*64 + tl] - cum[i*64 + s]) : 0.f;
                    PsT[s * 68 + tl] = Pblk[(size_t)(i*64 + tl) * CS_ + i*64 + s] * w;
                }
            } else {
                for (int idx = tid; idx < 64 * 64; idx += 256) {
                    int tl = idx >> 6, s = idx & 63;
                    PsT[s * 68 + tl] = Pblk[(size_t)(i*64 + tl) * CS_ + j*64 + s]
                                       * Esh[tl] * Rsh[s];
                }
            }
            __syncthreads();
            for (int sl = 0; sl < 64; sl++) {
                float4 x4 = *(const float4*)&xsm[sl * 68 + p0];
                float4 pw = *(const float4*)&PsT[sl * 68 + t0];
                float pr[4] = {pw.x, pw.y, pw.z, pw.w};
#pragma unroll
                for (int r = 0; r < 4; r++) {
                    yacc[r][0] = fmaf(pr[r], x4.x, yacc[r][0]);
                    yacc[r][1] = fmaf(pr[r], x4.y, yacc[r][1]);
                    yacc[r][2] = fmaf(pr[r], x4.z, yacc[r][2]);
                    yacc[r][3] = fmaf(pr[r], x4.w, yacc[r][3]);
                }
            }
        }
        {
#pragma unroll
            for (int r = 0; r < 4; r++) {
                size_t tg = rowbase + i * 64 + t0 + r;
                float4 o = {yacc[r][0], yacc[r][1], yacc[r][2], yacc[r][3]};
                *(float4*)&ydiag[(tg * NH_ + h) * HD_ + p0] = o;
            }
        }
    }
    {
        int n0 = ty * 8;
        size_t base = ((size_t)((b * NC_ + c) * NH_ + h)) * HD_;
#pragma unroll
        for (int r = 0; r < 4; r++) {
            float4 o0 = {stacc[r][0], stacc[r][1], stacc[r][2], stacc[r][3]};
            float4 o1 = {stacc[r][4], stacc[r][5], stacc[r][6], stacc[r][7]};
            float* dst = states + (base + p0 + r) * ST_ + n0;
            *(float4*)dst = o0;
            *(float4*)(dst + 4) = o1;
        }
    }
}

// ---------------- inter-chunk recurrence -----------------------------------
__global__ void interchunk_kernel(const float* __restrict__ states,
                                  const float* __restrict__ alast,
                                  float* __restrict__ prev)
{
    int bh = blockIdx.x;
    int b = bh >> 6, h = bh & 63;
    float dec[NC_];
#pragma unroll
    for (int c = 0; c < NC_; c++)
        dec[c] = expf(alast[(b * NH_ + h) * NC_ + c]);
    for (int e = threadIdx.x; e < HD_ * ST_; e += 256) {
        float run = 0.f;
#pragma unroll
        for (int c = 0; c < NC_; c++) {
            size_t idx = ((size_t)((b * NC_ + c) * NH_ + h)) * (HD_ * ST_) + e;
            prev[idx] = run;
            run = fmaf(run, dec[c] - 1.f, run);
            run = run + states[idx];
        }
    }
}

// ---------------- Y_off + D-skip, accumulate into y ------------------------
__global__ __launch_bounds__(256, 2) void scan_off_kernel(
    const float* __restrict__ xbc, const float* __restrict__ cumg,
    const float* __restrict__ prev, const float* __restrict__ Dv,
    float* __restrict__ y)
{
    const int h = blockIdx.x, c = blockIdx.y, b = blockIdx.z;
    const int tid = threadIdx.x;
    extern __shared__ float sm[];
    float* pvsT = sm;                  // [128][68]  (n, p)
    float* CsT  = pvsT + 128 * 68;     // [128][68]  (n, t)
    float* esh  = CsT + 128 * 68;      // [256]
    size_t sbase = ((size_t)((b * NC_ + c) * NH_ + h)) * (HD_ * ST_);
    for (int idx = tid; idx < 64 * 128; idx += 256) {
        int p = idx >> 7, n = idx & 127;
        pvsT[n * 68 + p] = prev[sbase + idx];
    }
    esh[tid] = expf(cumg[(size_t)(b * NH_ + h) * Ll + c * CS_ + tid]);
    const float Dh = Dv[h];
    const int tx = tid & 15, ty = tid >> 4;
    const size_t rowbase = (size_t)(b * Ll + c * CS_);
    for (int ti = 0; ti < 4; ti++) {
        __syncthreads();
        for (int idx = tid; idx < 64 * 128; idx += 256) {
            int tl = idx >> 7, n = idx & 127;
            CsT[n * 68 + tl] =
                xbc[(rowbase + ti * 64 + tl) * CONVD_ + (INTER_ + ST_) + n];
        }
        __syncthreads();
        int t0 = ty * 4, p0 = tx * 4;
        float acc[4][4];
#pragma unroll
        for (int r = 0; r < 4; r++)
#pragma unroll
            for (int q = 0; q < 4; q++) acc[r][q] = 0.f;
        for (int n = 0; n < 128; n++) {
            float4 c4 = *(const float4*)&CsT[n * 68 + t0];
            float4 p4 = *(const float4*)&pvsT[n * 68 + p0];
            float cr[4] = {c4.x, c4.y, c4.z, c4.w};
            float pv[4] = {p4.x, p4.y, p4.z, p4.w};
#pragma unroll
            for (int r = 0; r < 4; r++)
#pragma unroll
                for (int q = 0; q < 4; q++)
                    acc[r][q] = fmaf(cr[r], pv[q], acc[r][q]);
        }
#pragma unroll
        for (int r = 0; r < 4; r++) {
            size_t tg = rowbase + ti * 64 + t0 + r;
            float e = esh[ti * 64 + t0 + r];
            float* yp = y + (tg * NH_ + h) * HD_ + p0;
            float4 yv = *(float4*)yp;
            const float4 xv = *(const float4*)&xbc[tg * CONVD_ + h * HD_ + p0];
            yv.x += acc[r][0] * e + Dh * xv.x;
            yv.y += acc[r][1] * e + Dh * xv.y;
            yv.z += acc[r][2] * e + Dh * xv.z;
            yv.w += acc[r][3] * e + Dh * xv.w;
            *(float4*)yp = yv;
        }
    }
}

// ---------------- gated RMSNorm -> fp16 A for GEMM2 ------------------------
__global__ __launch_bounds__(256) void gated_norm_kernel(
    const float* __restrict__ proj, const float* __restrict__ y,
    const float* __restrict__ nw, __half* __restrict__ gf)
{
    int row = blockIdx.x;
    int tid = threadIdx.x;
    float gv[16];
    float ss = 0.f;
    const float* yr = y + (size_t)row * INTER_;
    const float* gr = proj + (size_t)row * PROJ_;
#pragma unroll
    for (int k = 0; k < 16; k++) {
        int idx = tid + k * 256;
        float gt = gr[idx];
        float s = 1.f / (1.f + expf(-gt));
        float v = yr[idx] * gt * s;
        gv[k] = v;
        ss = fmaf(v, v, ss);
    }
    __shared__ float red[256];
    red[tid] = ss;
    __syncthreads();
    for (int off = 128; off > 0; off >>= 1) {
        if (tid < off) red[tid] += red[tid + off];
        __syncthreads();
    }
    float scale = rsqrtf(red[0] / (float)INTER_ + 1e-5f);
#pragma unroll
    for (int k = 0; k < 16; k++) {
        int idx = tid + k * 256;
        gf[(size_t)row * INTER_ + idx] = __float2half_rn(gv[k] * scale * nw[idx]);
    }
}

// ---------------- launch ----------------------------------------------------
extern "C" void kernel_launch(void* const* d_in, const int* in_sizes, int n_in,
                              void* d_out, int out_size)
{
    const float* hidden  = (const float*)d_in[0];
    const float* in_w    = (const float*)d_in[1];
    const float* in_b    = (const float*)d_in[2];
    const float* conv_w  = (const float*)d_in[3];
    const float* dt_bias = (const float*)d_in[4];
    const float* A_log   = (const float*)d_in[5];
    const float* Dv      = (const float*)d_in[6];
    const float* norm_w  = (const float*)d_in[7];
    const float* out_w   = (const float*)d_in[8];
    const float* out_b   = (const float*)d_in[9];
    float* out = (float*)d_out;

    float *proj, *xbc, *y, *states, *prev, *cum, *al, *Pm;
    __half *Af, *W1h, *W1l, *W2h, *W2l;
    cudaGetSymbolAddress((void**)&proj,   g_proj);
    cudaGetSymbolAddress((void**)&xbc,    g_xbc);
    cudaGetSymbolAddress((void**)&y,      g_y);
    cudaGetSymbolAddress((void**)&states, g_states);
    cudaGetSymbolAddress((void**)&prev,   g_prev);
    cudaGetSymbolAddress((void**)&cum,    g_cum);
    cudaGetSymbolAddress((void**)&al,     g_alast);
    cudaGetSymbolAddress((void**)&Pm,     g_P);
    cudaGetSymbolAddress((void**)&Af,     g_Af);
    cudaGetSymbolAddress((void**)&W1h,    g_W1h);
    cudaGetSymbolAddress((void**)&W1l,    g_W1l);
    cudaGetSymbolAddress((void**)&W2h,    g_W2h);
    cudaGetSymbolAddress((void**)&W2l,    g_W2l);

    const int SMEM_PMAT  = (128 * 68 * 2) * 4;
    const int SMEM_INTRA = (64*68*2 + 64*132 + 256*3 + 128) * 4;
    const int SMEM_OFF   = (128*68*2 + 256) * 4;
    cudaFuncSetAttribute(pmat_kernel,
                         cudaFuncAttributeMaxDynamicSharedMemorySize, SMEM_PMAT);
    cudaFuncSetAttribute(scan_intra_kernel,
                         cudaFuncAttributeMaxDynamicSharedMemorySize, SMEM_INTRA);
    cudaFuncSetAttribute(scan_off_kernel,
                         cudaFuncAttributeMaxDynamicSharedMemorySize, SMEM_OFF);
    cudaFuncSetAttribute(tc_gemm_bias,
                         cudaFuncAttributeMaxDynamicSharedMemorySize, GSMEM);

    // 0. fp16 conversions
    {
        size_t n4 = (size_t)MT * HIDDEN_ / 4;
        cvt_fp16_kernel<<<(int)((n4 + 255) / 256), 256>>>(
            (const float4*)hidden, (__half2*)Af, n4);
        size_t n4v = (size_t)PROJ_ * HIDDEN_ / 4, n4t = (size_t)NP1 * HIDDEN_ / 4;
        cvt_split_fp16_kernel<<<(int)((n4t + 255) / 256), 256>>>(
            (const float4*)in_w, (__half2*)W1h, (__half2*)W1l, n4v, n4t);
        n4 = (size_t)HIDDEN_ * INTER_ / 4;
        cvt_split_fp16_kernel<<<(int)((n4 + 255) / 256), 256>>>(
            (const float4*)out_w, (__half2*)W2h, (__half2*)W2l, n4, n4);
    }

    // 1. in_proj GEMM + bias (2-pass fp16 mma.sync, 2 CTAs/SM)
    tc_gemm_bias<<<dim3(NP1 / 64, MT / 128), 256, GSMEM>>>(
        Af, W1h, W1l, in_b, proj, PROJ_, HIDDEN_);

    // 2. causal depthwise conv + SiLU
    conv_silu_kernel<<<(Bb * Ll * CONVD_ + 255) / 256, 256>>>(proj, conv_w, xbc);

    // 2b. shared P = C * B^T per (b, chunk)
    pmat_kernel<<<dim3(10, NC_, Bb), 256, SMEM_PMAT>>>(xbc, Pm);

    // 3. intra-chunk scan (per head, reusing P)
    scan_intra_kernel<<<dim3(NH_, NC_, Bb), 256, SMEM_INTRA>>>(
        proj, xbc, Pm, dt_bias, A_log, y, states, cum, al);

    // 4. inter-chunk recurrence
    interchunk_kernel<<<Bb * NH_, 256>>>(states, al, prev);

    // 5. inter-chunk output contribution + D skip
    scan_off_kernel<<<dim3(NH_, NC_, Bb), 256, SMEM_OFF>>>(xbc, cum, prev, Dv, y);

    // 6. gated RMSNorm -> fp16 A for GEMM2 (reuses Af)
    gated_norm_kernel<<<MT, 256>>>(proj, y, norm_w, Af);

    // 7. out_proj GEMM + bias (2-pass fp16 mma.sync, 2 CTAs/SM)
    tc_gemm_bias<<<dim3(HIDDEN_ / 64, MT / 128), 256, GSMEM>>>(
        Af, W2h, W2l, out_b, out, HIDDEN_, INTER_);
}